// round 1
// baseline (speedup 1.0000x reference)
#include <cuda_runtime.h>
#include <cstdint>
#include <cstddef>

#define B 128
#define P 196
#define F 2048
#define H 512
#define NF 512
#define E 512
#define V 10000
#define L 20
#define T 19
#define XK 3072          // E + F + H concat for the fused gates GEMM
#define BN_SCALE 0.9999950000374997f   // 1/sqrt(1+1e-5)

typedef unsigned long long ull;

// ---------------- scratch (static device globals; no allocation) ----------------
__device__ float g_feat[B * F];
__device__ float g_feat_att[(size_t)B * P * NF];     // 51.4 MB
__device__ float g_h[2][B * H];
__device__ float g_c[B * H];
__device__ float g_hWha[B * NF];
__device__ float g_e[B * P];
__device__ float g_alpha[B * P];
__device__ float g_ctx[B * F];
__device__ float g_xcat[B * XK];
__device__ float g_gates[B * 4 * H];
__device__ float g_Wcat[(size_t)4 * H * XK];         // [Wih | Whh] 25 MB
__device__ float g_bihh[4 * H];
__device__ float g_part[5242880];                    // split-K partials (max 4*128*10000)

// ---------------- f32x2 packed-FMA helpers (Blackwell double-rate fp32) ----------
__device__ __forceinline__ ull pk2(float lo, float hi) {
    ull r; asm("mov.b64 %0, {%1, %2};" : "=l"(r) : "f"(lo), "f"(hi)); return r;
}
__device__ __forceinline__ ull f2fma(ull a, ull b, ull c) {
    ull d; asm("fma.rn.f32x2 %0, %1, %2, %3;" : "=l"(d) : "l"(a), "l"(b), "l"(c)); return d;
}
__device__ __forceinline__ void upk2(ull v, float& x, float& y) {
    asm("mov.b64 {%0, %1}, %2;" : "=f"(x), "=f"(y) : "l"(v));
}
__device__ __forceinline__ float sigmoidf(float x) { return 1.0f / (1.0f + expf(-x)); }

// ---------------- generic NT SGEMM: C = A(MxK) * B(NxK)^T --------------------
// BM=BN=128, BK=8, 256 threads, 8x8 microtile via f32x2 FMA.
// gridDim.z = S split-K slices; each slice writes its private partial C + z*M*N.
// bias applied only when caller guarantees S==1 (feat_att).
__global__ __launch_bounds__(256) void sgemm_nt(
    const float* __restrict__ A, const float* __restrict__ Bw,
    float* __restrict__ C, int M, int N, int K,
    const float* __restrict__ bias)
{
    __shared__ float As[8][128];
    __shared__ float Bs[8][128];
    const int tid = threadIdx.x;
    const int bn = blockIdx.x * 128;
    const int bm = blockIdx.y * 128;
    const int S  = gridDim.z;
    const int Ks = K / S;
    const int z  = blockIdx.z;

    const int lr = tid >> 1;          // 0..127
    const int lc = (tid & 1) * 4;     // 0 or 4
    const float* aL = A + (size_t)(bm + lr) * K + (size_t)z * Ks + lc;
    const int brow = bn + lr;
    const float* bL = Bw + (size_t)brow * K + (size_t)z * Ks + lc;
    const bool bok = brow < N;

    const int tx = tid & 15;
    const int ty = tid >> 4;

    ull acc[8][4];
#pragma unroll
    for (int i = 0; i < 8; i++)
#pragma unroll
        for (int j = 0; j < 4; j++) acc[i][j] = 0ULL;

    for (int k0 = 0; k0 < Ks; k0 += 8) {
        float4 av = *(const float4*)(aL + k0);
        float4 bw = bok ? *(const float4*)(bL + k0) : make_float4(0.f, 0.f, 0.f, 0.f);
        As[lc + 0][lr] = av.x; As[lc + 1][lr] = av.y; As[lc + 2][lr] = av.z; As[lc + 3][lr] = av.w;
        Bs[lc + 0][lr] = bw.x; Bs[lc + 1][lr] = bw.y; Bs[lc + 2][lr] = bw.z; Bs[lc + 3][lr] = bw.w;
        __syncthreads();
#pragma unroll
        for (int k = 0; k < 8; k++) {
            float4 a0 = *(const float4*)&As[k][ty * 8];
            float4 a1 = *(const float4*)&As[k][ty * 8 + 4];
            float4 b0 = *(const float4*)&Bs[k][tx * 8];
            float4 b1 = *(const float4*)&Bs[k][tx * 8 + 4];
            ull bp0 = pk2(b0.x, b0.y), bp1 = pk2(b0.z, b0.w);
            ull bp2 = pk2(b1.x, b1.y), bp3 = pk2(b1.z, b1.w);
            float aa[8] = {a0.x, a0.y, a0.z, a0.w, a1.x, a1.y, a1.z, a1.w};
#pragma unroll
            for (int i = 0; i < 8; i++) {
                ull ap = pk2(aa[i], aa[i]);
                acc[i][0] = f2fma(ap, bp0, acc[i][0]);
                acc[i][1] = f2fma(ap, bp1, acc[i][1]);
                acc[i][2] = f2fma(ap, bp2, acc[i][2]);
                acc[i][3] = f2fma(ap, bp3, acc[i][3]);
            }
        }
        __syncthreads();
    }

    float* Cp = C + (size_t)z * M * N;
    const int cb = bn + tx * 8;
#pragma unroll
    for (int i = 0; i < 8; i++) {
        float* crow = Cp + (size_t)(bm + ty * 8 + i) * N;
#pragma unroll
        for (int j = 0; j < 4; j++) {
            float x, y; upk2(acc[i][j], x, y);
            int col = cb + 2 * j;
            if (col < N)     crow[col]     = bias ? x + bias[col]     : x;
            if (col + 1 < N) crow[col + 1] = bias ? y + bias[col + 1] : y;
        }
    }
}

// ---------------- small kernels ----------------
__global__ void mean_kernel(const float* __restrict__ enc, float* __restrict__ feat) {
    int f = blockIdx.x * 256 + threadIdx.x;   // grid (8, B)
    int b = blockIdx.y;
    const float* p0 = enc + (size_t)b * P * F + f;
    float s = 0.f;
#pragma unroll 4
    for (int p = 0; p < P; p++) s += p0[(size_t)p * F];
    feat[b * F + f] = s * (1.0f / (float)P);
}

__global__ void wcat_kernel(const float* __restrict__ Wih, const float* __restrict__ Whh,
                            float* __restrict__ Wcat) {
    int k = blockIdx.x * 256 + threadIdx.x;   // grid (12, 4H)
    int n = blockIdx.y;
    Wcat[(size_t)n * XK + k] = (k < (E + F)) ? Wih[(size_t)n * (E + F) + k]
                                             : Whh[(size_t)n * H + (k - (E + F))];
}

__global__ void bihh_kernel(const float* __restrict__ bih, const float* __restrict__ bhh,
                            float* __restrict__ out) {
    int n = blockIdx.x * 256 + threadIdx.x;   // grid (8)
    out[n] = bih[n] + bhh[n];
}

__global__ void epi_hc_kernel(const float* __restrict__ part, int S,
                              const float* __restrict__ bias, const float* __restrict__ gamma,
                              const float* __restrict__ beta, float* __restrict__ out) {
    int n = blockIdx.x * 256 + threadIdx.x;   // grid (2, B), N=H
    int m = blockIdx.y;
    int idx = m * H + n;
    float s = 0.f;
    for (int z = 0; z < S; z++) s += part[(size_t)z * B * H + idx];
    float x = sigmoidf(s + bias[n]);
    out[idx] = gamma[n] * (x * BN_SCALE) + beta[n];
}

__global__ void epi_bias_kernel(const float* __restrict__ part, int S, int N,
                                const float* __restrict__ bias, float* __restrict__ out) {
    int n = blockIdx.x * 256 + threadIdx.x;   // grid (N/256, B)
    int m = blockIdx.y;
    int MN = (int)gridDim.y * N;
    int idx = m * N + n;
    float s = 0.f;
    for (int z = 0; z < S; z++) s += part[(size_t)z * MN + idx];
    out[idx] = s + bias[n];
}

__global__ void epi_gate_kernel(const float* __restrict__ part, int S,
                                const float* __restrict__ bfb, const float* __restrict__ ctx,
                                float* __restrict__ xcat) {
    int n = blockIdx.x * 256 + threadIdx.x;   // grid (8, B), N=F
    int m = blockIdx.y;
    int idx = m * F + n;
    float s = 0.f;
    for (int z = 0; z < S; z++) s += part[(size_t)z * B * F + idx];
    xcat[(size_t)m * XK + E + n] = sigmoidf(s + bfb[n]) * ctx[idx];
}

__global__ void epi_preds_kernel(const float* __restrict__ part, int S,
                                 const float* __restrict__ bfc, const int* __restrict__ lens,
                                 int t, float* __restrict__ out) {
    int n = blockIdx.x * 256 + threadIdx.x;   // grid (40, B)
    if (n >= V) return;
    int m = blockIdx.y;
    float s = 0.f;
    for (int z = 0; z < S; z++) s += part[(size_t)z * B * V + (size_t)m * V + n];
    float mf = (t < lens[m] - 1) ? 1.f : 0.f;
    out[((size_t)m * T + t) * V + n] = (s + bfc[n]) * mf;
}

// e[b,p] = sum_n relu(feat_att[b,p,n] + hWha[b,n]) * Wv[n] + bv
__global__ __launch_bounds__(256) void att_e_kernel(
    const float* __restrict__ fa, const float* __restrict__ hw,
    const float* __restrict__ Wv, const float* __restrict__ bv,
    float* __restrict__ e) {
    int warp = threadIdx.x >> 5, lane = threadIdx.x & 31;
    int gid = blockIdx.x * 8 + warp;          // grid (B*P/8) = 3136
    int b = gid / P;
    const float4* fav = (const float4*)(fa + (size_t)gid * NF);
    const float4* hwv = (const float4*)(hw + (size_t)b * NF);
    const float4* wvv = (const float4*)Wv;
    float s = 0.f;
#pragma unroll
    for (int r = 0; r < 4; r++) {
        int i = lane + r * 32;
        float4 x = fav[i], y = hwv[i], w = wvv[i];
        s += fmaxf(x.x + y.x, 0.f) * w.x;
        s += fmaxf(x.y + y.y, 0.f) * w.y;
        s += fmaxf(x.z + y.z, 0.f) * w.z;
        s += fmaxf(x.w + y.w, 0.f) * w.w;
    }
#pragma unroll
    for (int o = 16; o; o >>= 1) s += __shfl_xor_sync(0xffffffffu, s, o);
    if (lane == 0) e[gid] = s + bv[0];
}

__global__ void softmax_kernel(const float* __restrict__ e, float* __restrict__ alpha,
                               float* __restrict__ out_alpha, const int* __restrict__ lens, int t) {
    int b = blockIdx.x;                       // grid (B), 256 threads
    int p = threadIdx.x;
    __shared__ float red[256];
    float v = (p < P) ? e[b * P + p] : -1e30f;
    red[p] = v; __syncthreads();
    for (int o = 128; o; o >>= 1) { if (p < o) red[p] = fmaxf(red[p], red[p + o]); __syncthreads(); }
    float mx = red[0]; __syncthreads();
    float ex = (p < P) ? expf(v - mx) : 0.f;
    red[p] = ex; __syncthreads();
    for (int o = 128; o; o >>= 1) { if (p < o) red[p] += red[p + o]; __syncthreads(); }
    float inv = 1.0f / red[0];
    if (p < P) {
        float a = ex * inv;
        alpha[b * P + p] = a;
        float mf = (t < lens[b] - 1) ? 1.f : 0.f;
        out_alpha[((size_t)b * T + t) * P + p] = a * mf;
    }
}

__global__ void context_kernel(const float* __restrict__ enc, const float* __restrict__ alpha,
                               float* __restrict__ ctx) {
    __shared__ float sa[P];
    int b = blockIdx.y;                       // grid (8, B)
    int f = blockIdx.x * 256 + threadIdx.x;
    if (threadIdx.x < P) sa[threadIdx.x] = alpha[b * P + threadIdx.x];
    __syncthreads();
    const float* ep = enc + (size_t)b * P * F + f;
    float acc = 0.f;
#pragma unroll 4
    for (int p = 0; p < P; p++) acc += ep[(size_t)p * F] * sa[p];
    ctx[b * F + f] = acc;
}

__global__ void assemble_kernel(const float* __restrict__ emb, const int* __restrict__ caps,
                                const float* __restrict__ hprev, float* __restrict__ xcat, int t) {
    int idx = blockIdx.x * 256 + threadIdx.x; // grid (4, B), idx in [0,1024)
    int b = blockIdx.y;
    if (idx < E) {
        int tok = caps[b * L + t];
        xcat[(size_t)b * XK + idx] = emb[(size_t)tok * E + idx];
    } else {
        int j = idx - E;
        xcat[(size_t)b * XK + E + F + j] = hprev[b * H + j];
    }
}

__global__ void lstm_kernel(const float* __restrict__ gates, float* __restrict__ c,
                            float* __restrict__ hnext) {
    int j = blockIdx.x * 256 + threadIdx.x;   // grid (2, B)
    int b = blockIdx.y;
    const float* g = gates + (size_t)b * 4 * H;
    float ig = sigmoidf(g[j]);
    float fg = sigmoidf(g[j + H]);
    float gg = tanhf(g[j + 2 * H]);
    float og = sigmoidf(g[j + 3 * H]);
    float cn = fg * c[b * H + j] + ig * gg;
    c[b * H + j] = cn;
    hnext[b * H + j] = og * tanhf(cn);
}

// ---------------- host ----------------
static void gemm(const float* A, const float* Bw, float* C, int M, int N, int K, int S,
                 const float* bias) {
    dim3 grid((N + 127) / 128, M / 128, S);
    sgemm_nt<<<grid, 256>>>(A, Bw, C, M, N, K, bias);
}

extern "C" void kernel_launch(void* const* d_in, const int* in_sizes, int n_in,
                              void* d_out, int out_size) {
    const float* enc     = (const float*)d_in[0];
    const float* emb     = (const float*)d_in[1];
    const float* Wfa     = (const float*)d_in[2];
    const float* bfa     = (const float*)d_in[3];
    const float* Wha     = (const float*)d_in[4];
    const float* bha     = (const float*)d_in[5];
    const float* Wv      = (const float*)d_in[6];
    const float* bv      = (const float*)d_in[7];
    const float* Wh0     = (const float*)d_in[8];
    const float* bh0     = (const float*)d_in[9];
    const float* Wc0     = (const float*)d_in[10];
    const float* bc0     = (const float*)d_in[11];
    const float* gamma_h = (const float*)d_in[12];
    const float* beta_h  = (const float*)d_in[13];
    const float* gamma_c = (const float*)d_in[14];
    const float* beta_c  = (const float*)d_in[15];
    const float* Wfb     = (const float*)d_in[16];
    const float* bfb     = (const float*)d_in[17];
    const float* Wih     = (const float*)d_in[18];
    const float* Whh     = (const float*)d_in[19];
    const float* bih     = (const float*)d_in[20];
    const float* bhh     = (const float*)d_in[21];
    const float* Wfc     = (const float*)d_in[22];
    const float* bfc     = (const float*)d_in[23];
    const int*   caps    = (const int*)d_in[24];
    const int*   lens    = (const int*)d_in[25];

    float* out_pred  = (float*)d_out;
    float* out_alpha = out_pred + (size_t)B * T * V;

    float *p_feat, *p_fa, *p_h, *p_c, *p_hW, *p_e, *p_al, *p_ctx, *p_x, *p_g, *p_Wc, *p_bb, *p_part;
    cudaGetSymbolAddress((void**)&p_feat, g_feat);
    cudaGetSymbolAddress((void**)&p_fa,   g_feat_att);
    cudaGetSymbolAddress((void**)&p_h,    g_h);
    cudaGetSymbolAddress((void**)&p_c,    g_c);
    cudaGetSymbolAddress((void**)&p_hW,   g_hWha);
    cudaGetSymbolAddress((void**)&p_e,    g_e);
    cudaGetSymbolAddress((void**)&p_al,   g_alpha);
    cudaGetSymbolAddress((void**)&p_ctx,  g_ctx);
    cudaGetSymbolAddress((void**)&p_x,    g_xcat);
    cudaGetSymbolAddress((void**)&p_g,    g_gates);
    cudaGetSymbolAddress((void**)&p_Wc,   g_Wcat);
    cudaGetSymbolAddress((void**)&p_bb,   g_bihh);
    cudaGetSymbolAddress((void**)&p_part, g_part);

    // ---- precompute ----
    mean_kernel<<<dim3(F / 256, B), 256>>>(enc, p_feat);
    wcat_kernel<<<dim3(XK / 256, 4 * H), 256>>>(Wih, Whh, p_Wc);
    bihh_kernel<<<dim3(4 * H / 256), 256>>>(bih, bhh, p_bb);

    // h0 = bn(sigmoid(feat @ Wh0^T + bh0))
    gemm(p_feat, Wh0, p_part, B, H, F, 16, nullptr);
    epi_hc_kernel<<<dim3(H / 256, B), 256>>>(p_part, 16, bh0, gamma_h, beta_h, p_h);
    // c0
    gemm(p_feat, Wc0, p_part, B, H, F, 16, nullptr);
    epi_hc_kernel<<<dim3(H / 256, B), 256>>>(p_part, 16, bc0, gamma_c, beta_c, p_c);

    // feat_att = enc(25088x2048) @ Wfa^T + bfa
    gemm(enc, Wfa, p_fa, B * P, NF, F, 1, bfa);

    // ---- timestep loop (unrolled on host; ping-pong h buffers) ----
    for (int t = 0; t < T; t++) {
        float* hprev = p_h + (size_t)(t & 1) * B * H;
        float* hnext = p_h + (size_t)((t + 1) & 1) * B * H;

        // hWha = hprev @ Wha^T + bha
        gemm(hprev, Wha, p_part, B, NF, H, 16, nullptr);
        epi_bias_kernel<<<dim3(NF / 256, B), 256>>>(p_part, 16, NF, bha, p_hW);

        att_e_kernel<<<dim3(B * P / 8), 256>>>(p_fa, p_hW, Wv, bv, p_e);
        softmax_kernel<<<dim3(B), 256>>>(p_e, p_al, out_alpha, lens, t);
        context_kernel<<<dim3(F / 256, B), 256>>>(enc, p_al, p_ctx);

        // gate = sigmoid(hprev @ Wfb^T + bfb); xcat[:,E:E+F] = gate * ctx
        gemm(hprev, Wfb, p_part, B, F, H, 8, nullptr);
        epi_gate_kernel<<<dim3(F / 256, B), 256>>>(p_part, 8, bfb, p_ctx, p_x);

        assemble_kernel<<<dim3(4, B), 256>>>(emb, caps, hprev, p_x, t);

        // gates = xcat @ [Wih|Whh]^T + (bih + bhh)
        gemm(p_x, p_Wc, p_part, B, 4 * H, XK, 16, nullptr);
        epi_bias_kernel<<<dim3(4 * H / 256, B), 256>>>(p_part, 16, 4 * H, p_bb, p_g);

        lstm_kernel<<<dim3(H / 256, B), 256>>>(p_g, p_c, hnext);

        // preds = hnext @ Wfc^T + bfc, masked, strided into output
        gemm(hnext, Wfc, p_part, B, V, H, 4, nullptr);
        epi_preds_kernel<<<dim3((V + 255) / 256, B), 256>>>(p_part, 4, bfc, lens, t, out_pred);
    }
}

// round 4
// speedup vs baseline: 2.1131x; 2.1131x over previous
#include <cuda_runtime.h>
#include <cstdint>
#include <cstddef>

#define B 128
#define P 196
#define F 2048
#define H 512
#define NF 512
#define E 512
#define V 10000
#define L 20
#define T 19
#define NCAT 4608   // Wha(512) + Wfb(2048) + Whh(2048)
#define BN_SCALE 0.9999950000374997f   // 1/sqrt(1+1e-5)

typedef unsigned long long ull;

// ---------------- scratch (static device globals) ----------------
__device__ float g_feat[B * F];
__device__ float g_feat_att[(size_t)B * P * NF];       // 51.4 MB
__device__ float g_h[2][B * H];
__device__ float g_c[B * H];
__device__ float g_hWha[B * NF];
__device__ float g_e[B * P];
__device__ float g_alpha[B * P];
__device__ float g_gatepre[B * F];
__device__ float g_gatesH[B * 4 * H];
__device__ float g_xgc[B * F];
__device__ float g_Wcat3[(size_t)NCAT * H];            // 9.4 MB
__device__ float g_bihh[4 * H];
__device__ float g_embseq[(size_t)T * B * E];
__device__ float g_embW[(size_t)T * B * 4 * H];        // 19.9 MB
__device__ float g_part[6 * 1024 * 1024];              // split-K partials

// ---------------- f32x2 helpers ----------------
__device__ __forceinline__ ull pk2(float lo, float hi) {
    ull r; asm("mov.b64 %0, {%1, %2};" : "=l"(r) : "f"(lo), "f"(hi)); return r;
}
__device__ __forceinline__ ull f2fma(ull a, ull b, ull c) {
    ull d; asm("fma.rn.f32x2 %0, %1, %2, %3;" : "=l"(d) : "l"(a), "l"(b), "l"(c)); return d;
}
__device__ __forceinline__ void upk2(ull v, float& x, float& y) {
    asm("mov.b64 {%0, %1}, %2;" : "=f"(x), "=f"(y) : "l"(v));
}
__device__ __forceinline__ float sigmoidf(float x) { return 1.0f / (1.0f + expf(-x)); }

// ---------------- SGEMM: C = A(MxK,lda) * B(NxK,ldb)^T ----------------
// BM=BN=128, BK=16, 256 threads, 8x8 micro (4+4 split fragments), double-buffered.
// gridDim.z = S split-K slices writing private partials at C + z*M*N.
__global__ __launch_bounds__(256, 2) void sgemm_nt(
    const float* __restrict__ A, const float* __restrict__ Bw, float* __restrict__ C,
    int M, int N, int K, int lda, int ldb, const float* __restrict__ bias)
{
    __shared__ float As[2][16][128];
    __shared__ float Bs[2][16][128];
    const int tid = threadIdx.x;
    const int bn = blockIdx.x * 128, bm = blockIdx.y * 128;
    const int S = gridDim.z, z = blockIdx.z;
    const int Ks = K / S;
    const int lr = tid >> 1, lc = (tid & 1) * 8;
    const float* aP = A + (size_t)(bm + lr) * lda + (size_t)z * Ks + lc;
    const int brow = bn + lr;
    const bool bok = brow < N;
    const float* bP = Bw + (size_t)brow * ldb + (size_t)z * Ks + lc;
    const int tx = tid & 15, ty = tid >> 4;
    const int nsteps = Ks >> 4;

    float4 ra0 = *(const float4*)aP;
    float4 ra1 = *(const float4*)(aP + 4);
    float4 rb0 = bok ? *(const float4*)bP       : make_float4(0.f,0.f,0.f,0.f);
    float4 rb1 = bok ? *(const float4*)(bP + 4) : make_float4(0.f,0.f,0.f,0.f);
    int cur = 0;
    As[0][lc+0][lr]=ra0.x; As[0][lc+1][lr]=ra0.y; As[0][lc+2][lr]=ra0.z; As[0][lc+3][lr]=ra0.w;
    As[0][lc+4][lr]=ra1.x; As[0][lc+5][lr]=ra1.y; As[0][lc+6][lr]=ra1.z; As[0][lc+7][lr]=ra1.w;
    Bs[0][lc+0][lr]=rb0.x; Bs[0][lc+1][lr]=rb0.y; Bs[0][lc+2][lr]=rb0.z; Bs[0][lc+3][lr]=rb0.w;
    Bs[0][lc+4][lr]=rb1.x; Bs[0][lc+5][lr]=rb1.y; Bs[0][lc+6][lr]=rb1.z; Bs[0][lc+7][lr]=rb1.w;
    __syncthreads();

    ull acc[8][4];
#pragma unroll
    for (int i = 0; i < 8; i++)
#pragma unroll
        for (int j = 0; j < 4; j++) acc[i][j] = 0ULL;

    for (int s = 0; s < nsteps; s++) {
        if (s + 1 < nsteps) {
            const float* a2 = aP + (s + 1) * 16;
            const float* b2 = bP + (s + 1) * 16;
            ra0 = *(const float4*)a2; ra1 = *(const float4*)(a2 + 4);
            if (bok) { rb0 = *(const float4*)b2; rb1 = *(const float4*)(b2 + 4); }
        }
#pragma unroll
        for (int k = 0; k < 16; k++) {
            float4 a0 = *(const float4*)&As[cur][k][ty * 4];
            float4 a1 = *(const float4*)&As[cur][k][64 + ty * 4];
            float4 b0 = *(const float4*)&Bs[cur][k][tx * 4];
            float4 b1 = *(const float4*)&Bs[cur][k][64 + tx * 4];
            ull bp0 = pk2(b0.x, b0.y), bp1 = pk2(b0.z, b0.w);
            ull bp2 = pk2(b1.x, b1.y), bp3 = pk2(b1.z, b1.w);
            float aa[8] = {a0.x, a0.y, a0.z, a0.w, a1.x, a1.y, a1.z, a1.w};
#pragma unroll
            for (int i = 0; i < 8; i++) {
                ull ap = pk2(aa[i], aa[i]);
                acc[i][0] = f2fma(ap, bp0, acc[i][0]);
                acc[i][1] = f2fma(ap, bp1, acc[i][1]);
                acc[i][2] = f2fma(ap, bp2, acc[i][2]);
                acc[i][3] = f2fma(ap, bp3, acc[i][3]);
            }
        }
        if (s + 1 < nsteps) {
            int nxt = cur ^ 1;
            As[nxt][lc+0][lr]=ra0.x; As[nxt][lc+1][lr]=ra0.y; As[nxt][lc+2][lr]=ra0.z; As[nxt][lc+3][lr]=ra0.w;
            As[nxt][lc+4][lr]=ra1.x; As[nxt][lc+5][lr]=ra1.y; As[nxt][lc+6][lr]=ra1.z; As[nxt][lc+7][lr]=ra1.w;
            Bs[nxt][lc+0][lr]=rb0.x; Bs[nxt][lc+1][lr]=rb0.y; Bs[nxt][lc+2][lr]=rb0.z; Bs[nxt][lc+3][lr]=rb0.w;
            Bs[nxt][lc+4][lr]=rb1.x; Bs[nxt][lc+5][lr]=rb1.y; Bs[nxt][lc+6][lr]=rb1.z; Bs[nxt][lc+7][lr]=rb1.w;
            __syncthreads();
            cur = nxt;
        }
    }

    float* Cp = C + (size_t)z * M * N;
    const int c0 = bn + tx * 4, c1 = bn + 64 + tx * 4;
#pragma unroll
    for (int i = 0; i < 8; i++) {
        int row = bm + ((i < 4) ? ty * 4 + i : 64 + ty * 4 + (i - 4));
        float* cr = Cp + (size_t)row * N;
        float x0, x1, x2, x3;
        upk2(acc[i][0], x0, x1); upk2(acc[i][1], x2, x3);
        if (bias) {
            if (c0     < N) cr[c0]     = x0 + bias[c0];
            if (c0 + 1 < N) cr[c0 + 1] = x1 + bias[c0 + 1];
            if (c0 + 2 < N) cr[c0 + 2] = x2 + bias[c0 + 2];
            if (c0 + 3 < N) cr[c0 + 3] = x3 + bias[c0 + 3];
        } else {
            if (c0     < N) cr[c0]     = x0;
            if (c0 + 1 < N) cr[c0 + 1] = x1;
            if (c0 + 2 < N) cr[c0 + 2] = x2;
            if (c0 + 3 < N) cr[c0 + 3] = x3;
        }
        upk2(acc[i][2], x0, x1); upk2(acc[i][3], x2, x3);
        if (bias) {
            if (c1     < N) cr[c1]     = x0 + bias[c1];
            if (c1 + 1 < N) cr[c1 + 1] = x1 + bias[c1 + 1];
            if (c1 + 2 < N) cr[c1 + 2] = x2 + bias[c1 + 2];
            if (c1 + 3 < N) cr[c1 + 3] = x3 + bias[c1 + 3];
        } else {
            if (c1     < N) cr[c1]     = x0;
            if (c1 + 1 < N) cr[c1 + 1] = x1;
            if (c1 + 2 < N) cr[c1 + 2] = x2;
            if (c1 + 3 < N) cr[c1 + 3] = x3;
        }
    }
}

// ---------------- small kernels ----------------
__global__ void mean_kernel(const float* __restrict__ enc, float* __restrict__ feat) {
    int f = blockIdx.x * 256 + threadIdx.x;   // grid (8, B)
    int b = blockIdx.y;
    const float* p0 = enc + (size_t)b * P * F + f;
    float s = 0.f;
#pragma unroll 4
    for (int p = 0; p < P; p++) s += p0[(size_t)p * F];
    feat[b * F + f] = s * (1.0f / (float)P);
}

__global__ void wcat3_kernel(const float* __restrict__ Wha, const float* __restrict__ Wfb,
                             const float* __restrict__ Whh, float* __restrict__ W) {
    int k = blockIdx.x * 256 + threadIdx.x;   // grid (2, NCAT)
    int n = blockIdx.y;
    const float* src = (n < 512) ? &Wha[(size_t)n * H]
                     : (n < 2560) ? &Wfb[(size_t)(n - 512) * H]
                                  : &Whh[(size_t)(n - 2560) * H];
    W[(size_t)n * H + k] = src[k];
}

__global__ void bihh_kernel(const float* __restrict__ bih, const float* __restrict__ bhh,
                            float* __restrict__ out) {
    int n = blockIdx.x * 256 + threadIdx.x;   // grid (8)
    out[n] = bih[n] + bhh[n];
}

__global__ void embgather_kernel(const float* __restrict__ emb, const int* __restrict__ caps,
                                 float* __restrict__ embseq) {
    int col = blockIdx.x * 256 + threadIdx.x; // grid (2, T*B)
    int r = blockIdx.y;
    int t = r / B, b = r % B;
    int tok = caps[b * L + t];
    embseq[(size_t)r * E + col] = emb[(size_t)tok * E + col];
}

__global__ void epi_hc_kernel(const float* __restrict__ part, int S,
                              const float* __restrict__ bias, const float* __restrict__ gamma,
                              const float* __restrict__ beta, float* __restrict__ out) {
    int n = blockIdx.x * 256 + threadIdx.x;   // grid (2, B)
    int m = blockIdx.y;
    int idx = m * H + n;
    float s = 0.f;
    for (int z = 0; z < S; z++) s += part[(size_t)z * B * H + idx];
    float x = sigmoidf(s + bias[n]);
    out[idx] = gamma[n] * (x * BN_SCALE) + beta[n];
}

// sums S=4 partials of h @ [Wha|Wfb|Whh]^T (N=4608), scatters the three outputs
__global__ void epi_hW_kernel(const float* __restrict__ part,
                              const float* __restrict__ bha, const float* __restrict__ bfb,
                              const float* __restrict__ bihh,
                              float* __restrict__ hWha, float* __restrict__ gatepre,
                              float* __restrict__ gatesH) {
    int n = blockIdx.x * 256 + threadIdx.x;   // grid (18, B)
    int b = blockIdx.y;
    float s = 0.f;
#pragma unroll
    for (int z = 0; z < 4; z++) s += part[(size_t)z * B * NCAT + (size_t)b * NCAT + n];
    if (n < 512)        hWha[b * 512 + n]            = s + bha[n];
    else if (n < 2560)  gatepre[b * 2048 + (n - 512)] = s + bfb[n - 512];
    else                gatesH[b * 2048 + (n - 2560)] = s + bihh[n - 2560];
}

// e[b,p] = sum_n relu(feat_att[b,p,n] + hWha[b,n]) * Wv[n] + bv
__global__ __launch_bounds__(256) void att_e_kernel(
    const float* __restrict__ fa, const float* __restrict__ hw,
    const float* __restrict__ Wv, const float* __restrict__ bv, float* __restrict__ e) {
    int warp = threadIdx.x >> 5, lane = threadIdx.x & 31;
    int gid = blockIdx.x * 8 + warp;          // grid (B*P/8)
    int b = gid / P;
    const float4* fav = (const float4*)(fa + (size_t)gid * NF);
    const float4* hwv = (const float4*)(hw + (size_t)b * NF);
    const float4* wvv = (const float4*)Wv;
    float s = 0.f;
#pragma unroll
    for (int r = 0; r < 4; r++) {
        int i = lane + r * 32;
        float4 x = fav[i], y = hwv[i], w = wvv[i];
        s += fmaxf(x.x + y.x, 0.f) * w.x;
        s += fmaxf(x.y + y.y, 0.f) * w.y;
        s += fmaxf(x.z + y.z, 0.f) * w.z;
        s += fmaxf(x.w + y.w, 0.f) * w.w;
    }
#pragma unroll
    for (int o = 16; o; o >>= 1) s += __shfl_xor_sync(0xffffffffu, s, o);
    if (lane == 0) e[gid] = s + bv[0];
}

__global__ void softmax_kernel(const float* __restrict__ e, float* __restrict__ alpha,
                               float* __restrict__ out_alpha, const int* __restrict__ lens, int t) {
    int b = blockIdx.x;
    int p = threadIdx.x;
    __shared__ float red[256];
    float v = (p < P) ? e[b * P + p] : -1e30f;
    red[p] = v; __syncthreads();
    for (int o = 128; o; o >>= 1) { if (p < o) red[p] = fmaxf(red[p], red[p + o]); __syncthreads(); }
    float mx = red[0]; __syncthreads();
    float ex = (p < P) ? expf(v - mx) : 0.f;
    red[p] = ex; __syncthreads();
    for (int o = 128; o; o >>= 1) { if (p < o) red[p] += red[p + o]; __syncthreads(); }
    float inv = 1.0f / red[0];
    if (p < P) {
        float a = ex * inv;
        alpha[b * P + p] = a;
        float mf = (t < lens[b] - 1) ? 1.f : 0.f;
        out_alpha[((size_t)b * T + t) * P + p] = a * mf;
    }
}

// fused: context over P, then xgc = sigmoid(gatepre) * ctx
__global__ void ctx_gate_kernel(const float* __restrict__ enc, const float* __restrict__ alpha,
                                const float* __restrict__ gatepre, float* __restrict__ xgc) {
    __shared__ float sa[P];
    int b = blockIdx.y;                       // grid (8, B)
    int f = blockIdx.x * 256 + threadIdx.x;
    if (threadIdx.x < P) sa[threadIdx.x] = alpha[b * P + threadIdx.x];
    __syncthreads();
    const float* ep = enc + (size_t)b * P * F + f;
    float acc = 0.f;
#pragma unroll 4
    for (int p = 0; p < P; p++) acc += ep[(size_t)p * F] * sa[p];
    int idx = b * F + f;
    xgc[idx] = sigmoidf(gatepre[idx]) * acc;
}

// sums S=8 partials of xgc@WihF^T, adds gatesH + embW[t], runs LSTM cell
__global__ void lstm_epi_kernel(const float* __restrict__ part, const float* __restrict__ gatesH,
                                const float* __restrict__ embW, float* __restrict__ c,
                                float* __restrict__ hnext, int t) {
    int idx = blockIdx.x * 256 + threadIdx.x; // grid (B*H/256)
    int b = idx >> 9, j = idx & 511;
    float g4[4];
#pragma unroll
    for (int gi = 0; gi < 4; gi++) {
        int col = gi * 512 + j;
        float s = gatesH[b * 2048 + col] + embW[((size_t)t * B + b) * 2048 + col];
#pragma unroll
        for (int z = 0; z < 8; z++) s += part[(size_t)z * B * 2048 + b * 2048 + col];
        g4[gi] = s;
    }
    float ig = sigmoidf(g4[0]), fg = sigmoidf(g4[1]);
    float gg = tanhf(g4[2]),    og = sigmoidf(g4[3]);
    float cn = fg * c[idx] + ig * gg;
    c[idx] = cn;
    hnext[idx] = og * tanhf(cn);
}

__global__ void epi_preds_kernel(const float* __restrict__ part,
                                 const float* __restrict__ bfc, const int* __restrict__ lens,
                                 int t, float* __restrict__ out) {
    int n = blockIdx.x * 256 + threadIdx.x;   // grid (40, B)
    if (n >= V) return;
    int m = blockIdx.y;
    float s = 0.f;
#pragma unroll
    for (int z = 0; z < 4; z++) s += part[(size_t)z * B * V + (size_t)m * V + n];
    float mf = (t < lens[m] - 1) ? 1.f : 0.f;
    out[((size_t)m * T + t) * V + n] = (s + bfc[n]) * mf;
}

// ---------------- host ----------------
static void gemm(const float* A, const float* Bw, float* C, int M, int N, int K,
                 int lda, int ldb, int S, const float* bias) {
    dim3 grid((N + 127) / 128, M / 128, S);
    sgemm_nt<<<grid, 256>>>(A, Bw, C, M, N, K, lda, ldb, bias);
}

extern "C" void kernel_launch(void* const* d_in, const int* in_sizes, int n_in,
                              void* d_out, int out_size) {
    const float* enc     = (const float*)d_in[0];
    const float* emb     = (const float*)d_in[1];
    const float* Wfa     = (const float*)d_in[2];
    const float* bfa     = (const float*)d_in[3];
    const float* Wha     = (const float*)d_in[4];
    const float* bha     = (const float*)d_in[5];
    const float* Wv      = (const float*)d_in[6];
    const float* bv      = (const float*)d_in[7];
    const float* Wh0     = (const float*)d_in[8];
    const float* bh0     = (const float*)d_in[9];
    const float* Wc0     = (const float*)d_in[10];
    const float* bc0     = (const float*)d_in[11];
    const float* gamma_h = (const float*)d_in[12];
    const float* beta_h  = (const float*)d_in[13];
    const float* gamma_c = (const float*)d_in[14];
    const float* beta_c  = (const float*)d_in[15];
    const float* Wfb     = (const float*)d_in[16];
    const float* bfb     = (const float*)d_in[17];
    const float* Wih     = (const float*)d_in[18];
    const float* Whh     = (const float*)d_in[19];
    const float* bih     = (const float*)d_in[20];
    const float* bhh     = (const float*)d_in[21];
    const float* Wfc     = (const float*)d_in[22];
    const float* bfc     = (const float*)d_in[23];
    const int*   caps    = (const int*)d_in[24];
    const int*   lens    = (const int*)d_in[25];

    float* out_pred  = (float*)d_out;
    float* out_alpha = out_pred + (size_t)B * T * V;

    float *p_feat, *p_fa, *p_h, *p_c, *p_hW, *p_e, *p_al, *p_gp, *p_gH, *p_xgc,
          *p_W3, *p_bb, *p_es, *p_eW, *p_part;
    cudaGetSymbolAddress((void**)&p_feat, g_feat);
    cudaGetSymbolAddress((void**)&p_fa,   g_feat_att);
    cudaGetSymbolAddress((void**)&p_h,    g_h);
    cudaGetSymbolAddress((void**)&p_c,    g_c);
    cudaGetSymbolAddress((void**)&p_hW,   g_hWha);
    cudaGetSymbolAddress((void**)&p_e,    g_e);
    cudaGetSymbolAddress((void**)&p_al,   g_alpha);
    cudaGetSymbolAddress((void**)&p_gp,   g_gatepre);
    cudaGetSymbolAddress((void**)&p_gH,   g_gatesH);
    cudaGetSymbolAddress((void**)&p_xgc,  g_xgc);
    cudaGetSymbolAddress((void**)&p_W3,   g_Wcat3);
    cudaGetSymbolAddress((void**)&p_bb,   g_bihh);
    cudaGetSymbolAddress((void**)&p_es,   g_embseq);
    cudaGetSymbolAddress((void**)&p_eW,   g_embW);
    cudaGetSymbolAddress((void**)&p_part, g_part);

    // ---- precompute ----
    mean_kernel<<<dim3(F / 256, B), 256>>>(enc, p_feat);
    wcat3_kernel<<<dim3(H / 256, NCAT), 256>>>(Wha, Wfb, Whh, p_W3);
    bihh_kernel<<<dim3(4 * H / 256), 256>>>(bih, bhh, p_bb);
    embgather_kernel<<<dim3(E / 256, T * B), 256>>>(emb, caps, p_es);

    // h0/c0
    gemm(p_feat, Wh0, p_part, B, H, F, F, F, 16, nullptr);
    epi_hc_kernel<<<dim3(H / 256, B), 256>>>(p_part, 16, bh0, gamma_h, beta_h, p_h);
    gemm(p_feat, Wc0, p_part, B, H, F, F, F, 16, nullptr);
    epi_hc_kernel<<<dim3(H / 256, B), 256>>>(p_part, 16, bc0, gamma_c, beta_c, p_c);

    // embW[t,b,:] = emb_t @ Wih[:, :E]^T  for all t at once
    gemm(p_es, Wih, p_eW, T * B, 4 * H, E, E, E + F, 1, nullptr);

    // feat_att = enc @ Wfa^T + bfa
    gemm(enc, Wfa, p_fa, B * P, NF, F, F, F, 1, bfa);

    // ---- timestep loop ----
    for (int t = 0; t < T; t++) {
        float* hprev = p_h + (size_t)(t & 1) * B * H;
        float* hnext = p_h + (size_t)((t + 1) & 1) * B * H;

        // h @ [Wha|Wfb|Whh]^T  (N=4608), S=4 -> 144 blocks
        gemm(hprev, p_W3, p_part, B, NCAT, H, H, H, 4, nullptr);
        epi_hW_kernel<<<dim3(NCAT / 256, B), 256>>>(p_part, bha, bfb, p_bb, p_hW, p_gp, p_gH);

        att_e_kernel<<<dim3(B * P / 8), 256>>>(p_fa, p_hW, Wv, bv, p_e);
        softmax_kernel<<<dim3(B), 256>>>(p_e, p_al, out_alpha, lens, t);
        ctx_gate_kernel<<<dim3(F / 256, B), 256>>>(enc, p_al, p_gp, p_xgc);

        // xgc @ Wih[:, E:]^T  (N=2048, K=2048), S=8 -> 128 blocks
        gemm(p_xgc, Wih + E, p_part, B, 4 * H, F, F, E + F, 8, nullptr);
        lstm_epi_kernel<<<dim3(B * H / 256), 256>>>(p_part, p_gH, p_eW, p_c, hnext, t);

        // preds = hnext @ Wfc^T, S=4 -> 316 blocks
        gemm(hnext, Wfc, p_part, B, V, H, H, H, 4, nullptr);
        epi_preds_kernel<<<dim3((V + 255) / 256, B), 256>>>(p_part, bfc, lens, t, out_pred);
    }
}

// round 7
// speedup vs baseline: 2.3451x; 1.1098x over previous
#include <cuda_runtime.h>
#include <cuda_fp16.h>
#include <cstdint>
#include <cstddef>

#define B 128
#define P 196
#define F 2048
#define H 512
#define NF 512
#define E 512
#define V 10000
#define L 20
#define T 19
#define NCAT 4608   // Wha(512) + Wfb(2048) + Whh(2048)
#define BN_SCALE 0.9999950000374997f   // 1/sqrt(1+1e-5)

typedef unsigned long long ull;

// ---------------- scratch (static device globals) ----------------
__device__ float g_feat[B * F];
__device__ float g_feat_att[(size_t)B * P * NF];       // 51.4 MB
__device__ float g_h[2][B * H];
__device__ float g_c[B * H];
__device__ float g_hWha[B * NF];
__device__ float g_e[B * P];
__device__ float g_alpha[B * P];
__device__ float g_gatepre[B * F];
__device__ float g_gatesH[B * 4 * H];
__device__ float g_xgc[B * F];
__device__ float g_Wcat3[(size_t)NCAT * H];            // 9.4 MB
__device__ float g_bihh[4 * H];
__device__ float g_embseq[(size_t)T * B * E];
__device__ float g_embW[(size_t)T * B * 4 * H];        // 19.9 MB
__device__ float g_part[6 * 1024 * 1024];              // split-K partials

__device__ __forceinline__ float sigmoidf(float x) { return 1.0f / (1.0f + expf(-x)); }

// ---------------- mma.sync helpers (non-'a' ISA; compiles at target sm_103) ----------
__device__ __forceinline__ uint32_t smem_u32(const void* p) {
    uint32_t a;
    asm("{ .reg .u64 t; cvta.to.shared.u64 t, %1; cvt.u32.u64 %0, t; }" : "=r"(a) : "l"(p));
    return a;
}
__device__ __forceinline__ void ldsm4(uint32_t* r, uint32_t addr) {
    asm volatile("ldmatrix.sync.aligned.m8n8.x4.shared.b16 {%0,%1,%2,%3}, [%4];"
                 : "=r"(r[0]), "=r"(r[1]), "=r"(r[2]), "=r"(r[3]) : "r"(addr));
}
__device__ __forceinline__ void mma16816(float* c, const uint32_t* a, const uint32_t* b) {
    asm volatile(
        "mma.sync.aligned.m16n8k16.row.col.f32.f16.f16.f32 "
        "{%0,%1,%2,%3}, {%4,%5,%6,%7}, {%8,%9}, {%0,%1,%2,%3};"
        : "+f"(c[0]), "+f"(c[1]), "+f"(c[2]), "+f"(c[3])
        : "r"(a[0]), "r"(a[1]), "r"(a[2]), "r"(a[3]), "r"(b[0]), "r"(b[1]));
}
__device__ __forceinline__ uint32_t swz(uint32_t off) { return off ^ ((off >> 3) & 0x70); }

// split fp32 pair -> f16x2 hi word + f16x2 lo word
__device__ __forceinline__ void conv2h(float x, float y, uint32_t& hw, uint32_t& lw) {
    __half hx = __float2half_rn(x), hy = __float2half_rn(y);
    float rx = x - __half2float(hx);
    float ry = y - __half2float(hy);
    __half lx = __float2half_rn(rx), ly = __float2half_rn(ry);
    hw = ((uint32_t)__half_as_ushort(hy) << 16) | (uint32_t)__half_as_ushort(hx);
    lw = ((uint32_t)__half_as_ushort(ly) << 16) | (uint32_t)__half_as_ushort(lx);
}

// ============ tensor-core split-f16 GEMM: C = A(MxK,lda) @ B(NxK,ldb)^T ============
// 128x128 CTA tile, K-chunks of 64, double-buffered hi/lo f16 planes in smem,
// fp32 accumulation in registers via mma.sync (3 passes: AhBh + AhBl + AlBh).
// gridDim.z = S split-K slices -> private partials at C + z*M*N.
// Requires: M % 128 == 0, (K/S) % 128 == 0.
#define HG_SMEM (2 * 65536)
__global__ __launch_bounds__(256, 1) void hmma_gemm_nt(
    const float* __restrict__ A, const float* __restrict__ Bw, float* __restrict__ C,
    int M, int N, int K, int lda, int ldb, const float* __restrict__ bias)
{
    extern __shared__ char smem[];
    const uint32_t sbase = smem_u32(smem);
    const int tid = threadIdx.x, wid = tid >> 5, lane = tid & 31;
    const int bn = blockIdx.x * 128, bm = blockIdx.y * 128;
    const int z = blockIdx.z;
    const int Ks = K / (int)gridDim.z;
    const int nchunks = Ks >> 6;

    // ---- conversion-path indexing: thread handles row r, 32 cols at c0 ----
    const int r  = tid >> 1;
    const int c0 = (tid & 1) * 32;
    const float* aP = A + (size_t)(bm + r) * lda + (size_t)z * Ks + c0;
    const int brow = bn + r;
    const bool bok = brow < N;
    const float* bP = Bw + (size_t)brow * ldb + (size_t)z * Ks + c0;

    // ---- mma-path indexing: warps 4x2, warp tile 32(M) x 64(N) ----
    const int wm = wid & 3, wn = wid >> 2;
    const int m0 = wm * 32, n0w = wn * 64;
    const uint32_t arowb = (uint32_t)(m0 + (lane & 15)) * 128;
    const uint32_t acolp = ((lane >> 4) & 1) * 16;
    const uint32_t browb = (uint32_t)(n0w + (lane & 7) + ((lane & 16) ? 8 : 0)) * 128;
    const uint32_t bcolp = (lane & 8) ? 16u : 0u;

    float acc[2][8][4];
#pragma unroll
    for (int mi = 0; mi < 2; mi++)
#pragma unroll
        for (int ni = 0; ni < 8; ni++)
#pragma unroll
            for (int q = 0; q < 4; q++) acc[mi][ni][q] = 0.f;

    for (int ch = 0; ch < nchunks; ch++) {
        const int buf = ch & 1;
        const uint32_t base = (uint32_t)buf * 65536;   // byte offset in dyn smem
        if (ch >= 2) {
            asm volatile("bar.sync %0, %1;" :: "r"(1 + buf), "r"(512) : "memory");
        }
        // ---- load fp32, split into f16 hi/lo planes (SW128) ----
        {
            const float* src = aP + ch * 64;
#pragma unroll
            for (int g = 0; g < 4; g++) {
                float4 v0 = *(const float4*)(src + g * 8);
                float4 v1 = *(const float4*)(src + g * 8 + 4);
                uint32_t h0, l0, h1, l1, h2, l2, h3, l3;
                conv2h(v0.x, v0.y, h0, l0); conv2h(v0.z, v0.w, h1, l1);
                conv2h(v1.x, v1.y, h2, l2); conv2h(v1.z, v1.w, h3, l3);
                uint32_t sw = swz((uint32_t)r * 128 + (uint32_t)(c0 + g * 8) * 2);
                *(uint4*)(smem + base + sw)         = make_uint4(h0, h1, h2, h3);
                *(uint4*)(smem + base + 16384 + sw) = make_uint4(l0, l1, l2, l3);
            }
        }
        {
            const float* src = bP + ch * 64;
#pragma unroll
            for (int g = 0; g < 4; g++) {
                float4 v0 = bok ? *(const float4*)(src + g * 8)     : make_float4(0.f, 0.f, 0.f, 0.f);
                float4 v1 = bok ? *(const float4*)(src + g * 8 + 4) : make_float4(0.f, 0.f, 0.f, 0.f);
                uint32_t h0, l0, h1, l1, h2, l2, h3, l3;
                conv2h(v0.x, v0.y, h0, l0); conv2h(v0.z, v0.w, h1, l1);
                conv2h(v1.x, v1.y, h2, l2); conv2h(v1.z, v1.w, h3, l3);
                uint32_t sw = swz((uint32_t)r * 128 + (uint32_t)(c0 + g * 8) * 2);
                *(uint4*)(smem + base + 32768 + sw) = make_uint4(h0, h1, h2, h3);
                *(uint4*)(smem + base + 49152 + sw) = make_uint4(l0, l1, l2, l3);
            }
        }
        __syncthreads();

        // ---- MMA over the 64-K chunk: 4 k16 steps ----
        const uint32_t ahB = sbase + base;
        const uint32_t alB = ahB + 16384;
        const uint32_t bhB = ahB + 32768;
        const uint32_t blB = ahB + 49152;
#pragma unroll
        for (int ks = 0; ks < 4; ks++) {
            const uint32_t kb = (uint32_t)ks * 32;
            uint32_t ah[2][4], al[2][4];
#pragma unroll
            for (int mi = 0; mi < 2; mi++) {
                uint32_t ao = swz(arowb + (uint32_t)mi * 2048 + kb + acolp);
                ldsm4(ah[mi], ahB + ao);
                ldsm4(al[mi], alB + ao);
            }
            uint32_t bh[8][2], bl[8][2];
#pragma unroll
            for (int nj = 0; nj < 4; nj++) {
                uint32_t bo = swz(browb + (uint32_t)nj * 2048 + kb + bcolp);
                uint32_t t4[4];
                ldsm4(t4, bhB + bo);
                bh[2*nj][0] = t4[0]; bh[2*nj][1] = t4[1];
                bh[2*nj+1][0] = t4[2]; bh[2*nj+1][1] = t4[3];
                ldsm4(t4, blB + bo);
                bl[2*nj][0] = t4[0]; bl[2*nj][1] = t4[1];
                bl[2*nj+1][0] = t4[2]; bl[2*nj+1][1] = t4[3];
            }
#pragma unroll
            for (int mi = 0; mi < 2; mi++)
#pragma unroll
                for (int ni = 0; ni < 8; ni++) {
                    mma16816(acc[mi][ni], ah[mi], bh[ni]);
                    mma16816(acc[mi][ni], ah[mi], bl[ni]);
                    mma16816(acc[mi][ni], al[mi], bh[ni]);
                }
        }
        asm volatile("bar.arrive %0, %1;" :: "r"(1 + buf), "r"(512) : "memory");
    }

    // ---- epilogue: fp32 acc -> C partials ----
    float* Cp = C + (size_t)z * (size_t)M * N;
#pragma unroll
    for (int mi = 0; mi < 2; mi++) {
        const int row = bm + m0 + mi * 16 + (lane >> 2);
        float* cr1 = Cp + (size_t)row * N;
        float* cr2 = cr1 + (size_t)8 * N;
#pragma unroll
        for (int ni = 0; ni < 8; ni++) {
            const int col = bn + n0w + ni * 8 + 2 * (lane & 3);
            if (col < N) {
                float b0 = bias ? bias[col] : 0.f;
                cr1[col] = acc[mi][ni][0] + b0;
                cr2[col] = acc[mi][ni][2] + b0;
                if (col + 1 < N) {
                    float b1 = bias ? bias[col + 1] : 0.f;
                    cr1[col + 1] = acc[mi][ni][1] + b1;
                    cr2[col + 1] = acc[mi][ni][3] + b1;
                }
            }
        }
    }
}

// ---------------- small kernels ----------------
__global__ void mean_kernel(const float* __restrict__ enc, float* __restrict__ feat) {
    int f = blockIdx.x * 256 + threadIdx.x;   // grid (8, B)
    int b = blockIdx.y;
    const float* p0 = enc + (size_t)b * P * F + f;
    float s = 0.f;
#pragma unroll 4
    for (int p = 0; p < P; p++) s += p0[(size_t)p * F];
    feat[b * F + f] = s * (1.0f / (float)P);
}

__global__ void wcat3_kernel(const float* __restrict__ Wha, const float* __restrict__ Wfb,
                             const float* __restrict__ Whh, float* __restrict__ W) {
    int k = blockIdx.x * 256 + threadIdx.x;   // grid (2, NCAT)
    int n = blockIdx.y;
    const float* src = (n < 512) ? &Wha[(size_t)n * H]
                     : (n < 2560) ? &Wfb[(size_t)(n - 512) * H]
                                  : &Whh[(size_t)(n - 2560) * H];
    W[(size_t)n * H + k] = src[k];
}

__global__ void bihh_kernel(const float* __restrict__ bih, const float* __restrict__ bhh,
                            float* __restrict__ out) {
    int n = blockIdx.x * 256 + threadIdx.x;
    out[n] = bih[n] + bhh[n];
}

__global__ void embgather_kernel(const float* __restrict__ emb, const int* __restrict__ caps,
                                 float* __restrict__ embseq) {
    int col = blockIdx.x * 256 + threadIdx.x; // grid (2, T*B)
    int rrow = blockIdx.y;
    int t = rrow / B, b = rrow % B;
    int tok = caps[b * L + t];
    embseq[(size_t)rrow * E + col] = emb[(size_t)tok * E + col];
}

__global__ void epi_hc_kernel(const float* __restrict__ part, int S,
                              const float* __restrict__ bias, const float* __restrict__ gamma,
                              const float* __restrict__ beta, float* __restrict__ out) {
    int n = blockIdx.x * 256 + threadIdx.x;   // grid (2, B)
    int m = blockIdx.y;
    int idx = m * H + n;
    float s = 0.f;
    for (int zz = 0; zz < S; zz++) s += part[(size_t)zz * B * H + idx];
    float x = sigmoidf(s + bias[n]);
    out[idx] = gamma[n] * (x * BN_SCALE) + beta[n];
}

// sums S=4 partials of h @ [Wha|Wfb|Whh]^T (N=4608), scatters the three outputs
__global__ void epi_hW_kernel(const float* __restrict__ part,
                              const float* __restrict__ bha, const float* __restrict__ bfb,
                              const float* __restrict__ bihh,
                              float* __restrict__ hWha, float* __restrict__ gatepre,
                              float* __restrict__ gatesH) {
    int n = blockIdx.x * 256 + threadIdx.x;   // grid (18, B)
    int b = blockIdx.y;
    float s = 0.f;
#pragma unroll
    for (int zz = 0; zz < 4; zz++) s += part[(size_t)zz * B * NCAT + (size_t)b * NCAT + n];
    if (n < 512)        hWha[b * 512 + n]             = s + bha[n];
    else if (n < 2560)  gatepre[b * 2048 + (n - 512)]  = s + bfb[n - 512];
    else                gatesH[b * 2048 + (n - 2560)]  = s + bihh[n - 2560];
}

// e[b,p] = sum_n relu(feat_att[b,p,n] + hWha[b,n]) * Wv[n] + bv
__global__ __launch_bounds__(256) void att_e_kernel(
    const float* __restrict__ fa, const float* __restrict__ hw,
    const float* __restrict__ Wv, const float* __restrict__ bv, float* __restrict__ e) {
    int warp = threadIdx.x >> 5, lane = threadIdx.x & 31;
    int gid = blockIdx.x * 8 + warp;          // grid (B*P/8)
    int b = gid / P;
    const float4* fav = (const float4*)(fa + (size_t)gid * NF);
    const float4* hwv = (const float4*)(hw + (size_t)b * NF);
    const float4* wvv = (const float4*)Wv;
    float s = 0.f;
#pragma unroll
    for (int rr = 0; rr < 4; rr++) {
        int i = lane + rr * 32;
        float4 x = fav[i], y = hwv[i], w = wvv[i];
        s += fmaxf(x.x + y.x, 0.f) * w.x;
        s += fmaxf(x.y + y.y, 0.f) * w.y;
        s += fmaxf(x.z + y.z, 0.f) * w.z;
        s += fmaxf(x.w + y.w, 0.f) * w.w;
    }
#pragma unroll
    for (int o = 16; o; o >>= 1) s += __shfl_xor_sync(0xffffffffu, s, o);
    if (lane == 0) e[gid] = s + bv[0];
}

__global__ void softmax_kernel(const float* __restrict__ e, float* __restrict__ alpha,
                               float* __restrict__ out_alpha, const int* __restrict__ lens, int t) {
    int b = blockIdx.x;
    int p = threadIdx.x;
    __shared__ float red[256];
    float v = (p < P) ? e[b * P + p] : -1e30f;
    red[p] = v; __syncthreads();
    for (int o = 128; o; o >>= 1) { if (p < o) red[p] = fmaxf(red[p], red[p + o]); __syncthreads(); }
    float mx = red[0]; __syncthreads();
    float ex = (p < P) ? expf(v - mx) : 0.f;
    red[p] = ex; __syncthreads();
    for (int o = 128; o; o >>= 1) { if (p < o) red[p] += red[p + o]; __syncthreads(); }
    float inv = 1.0f / red[0];
    if (p < P) {
        float a = ex * inv;
        alpha[b * P + p] = a;
        float mf = (t < lens[b] - 1) ? 1.f : 0.f;
        out_alpha[((size_t)b * T + t) * P + p] = a * mf;
    }
}

// fused: context over P, then xgc = sigmoid(gatepre) * ctx
__global__ void ctx_gate_kernel(const float* __restrict__ enc, const float* __restrict__ alpha,
                                const float* __restrict__ gatepre, float* __restrict__ xgc) {
    __shared__ float sa[P];
    int b = blockIdx.y;                       // grid (8, B)
    int f = blockIdx.x * 256 + threadIdx.x;
    if (threadIdx.x < P) sa[threadIdx.x] = alpha[b * P + threadIdx.x];
    __syncthreads();
    const float* ep = enc + (size_t)b * P * F + f;
    float acc = 0.f;
#pragma unroll 4
    for (int p = 0; p < P; p++) acc += ep[(size_t)p * F] * sa[p];
    int idx = b * F + f;
    xgc[idx] = sigmoidf(gatepre[idx]) * acc;
}

// sums S=8 partials of xgc@WihF^T, adds gatesH + embW[t], runs LSTM cell
__global__ void lstm_epi_kernel(const float* __restrict__ part, const float* __restrict__ gatesH,
                                const float* __restrict__ embW, float* __restrict__ c,
                                float* __restrict__ hnext, int t) {
    int idx = blockIdx.x * 256 + threadIdx.x; // grid (B*H/256)
    int b = idx >> 9, j = idx & 511;
    float g4[4];
#pragma unroll
    for (int gi = 0; gi < 4; gi++) {
        int col = gi * 512 + j;
        float s = gatesH[b * 2048 + col] + embW[((size_t)t * B + b) * 2048 + col];
#pragma unroll
        for (int zz = 0; zz < 8; zz++) s += part[(size_t)zz * B * 2048 + b * 2048 + col];
        g4[gi] = s;
    }
    float ig = sigmoidf(g4[0]), fg = sigmoidf(g4[1]);
    float gg = tanhf(g4[2]),    og = sigmoidf(g4[3]);
    float cn = fg * c[idx] + ig * gg;
    c[idx] = cn;
    hnext[idx] = og * tanhf(cn);
}

// preds: S=1 partial + bias + mask, strided store
__global__ void epi_preds_kernel(const float* __restrict__ part,
                                 const float* __restrict__ bfc, const int* __restrict__ lens,
                                 int t, float* __restrict__ out) {
    int n = blockIdx.x * 256 + threadIdx.x;   // grid (40, B)
    if (n >= V) return;
    int m = blockIdx.y;
    float s = part[(size_t)m * V + n];
    float mf = (t < lens[m] - 1) ? 1.f : 0.f;
    out[((size_t)m * T + t) * V + n] = (s + bfc[n]) * mf;
}

// ---------------- host ----------------
static void tgemm(const float* A, const float* Bw, float* C, int M, int N, int K,
                  int lda, int ldb, int S, const float* bias) {
    dim3 grid((N + 127) / 128, M / 128, S);
    hmma_gemm_nt<<<grid, 256, HG_SMEM>>>(A, Bw, C, M, N, K, lda, ldb, bias);
}

extern "C" void kernel_launch(void* const* d_in, const int* in_sizes, int n_in,
                              void* d_out, int out_size) {
    const float* enc     = (const float*)d_in[0];
    const float* emb     = (const float*)d_in[1];
    const float* Wfa     = (const float*)d_in[2];
    const float* bfa     = (const float*)d_in[3];
    const float* Wha     = (const float*)d_in[4];
    const float* bha     = (const float*)d_in[5];
    const float* Wv      = (const float*)d_in[6];
    const float* bv      = (const float*)d_in[7];
    const float* Wh0     = (const float*)d_in[8];
    const float* bh0     = (const float*)d_in[9];
    const float* Wc0     = (const float*)d_in[10];
    const float* bc0     = (const float*)d_in[11];
    const float* gamma_h = (const float*)d_in[12];
    const float* beta_h  = (const float*)d_in[13];
    const float* gamma_c = (const float*)d_in[14];
    const float* beta_c  = (const float*)d_in[15];
    const float* Wfb     = (const float*)d_in[16];
    const float* bfb     = (const float*)d_in[17];
    const float* Wih     = (const float*)d_in[18];
    const float* Whh     = (const float*)d_in[19];
    const float* bih     = (const float*)d_in[20];
    const float* bhh     = (const float*)d_in[21];
    const float* Wfc     = (const float*)d_in[22];
    const float* bfc     = (const float*)d_in[23];
    const int*   caps    = (const int*)d_in[24];
    const int*   lens    = (const int*)d_in[25];

    float* out_pred  = (float*)d_out;
    float* out_alpha = out_pred + (size_t)B * T * V;

    cudaFuncSetAttribute(hmma_gemm_nt, cudaFuncAttributeMaxDynamicSharedMemorySize, HG_SMEM);

    float *p_feat, *p_fa, *p_h, *p_c, *p_hW, *p_e, *p_al, *p_gp, *p_gH, *p_xgc,
          *p_W3, *p_bb, *p_es, *p_eW, *p_part;
    cudaGetSymbolAddress((void**)&p_feat, g_feat);
    cudaGetSymbolAddress((void**)&p_fa,   g_feat_att);
    cudaGetSymbolAddress((void**)&p_h,    g_h);
    cudaGetSymbolAddress((void**)&p_c,    g_c);
    cudaGetSymbolAddress((void**)&p_hW,   g_hWha);
    cudaGetSymbolAddress((void**)&p_e,    g_e);
    cudaGetSymbolAddress((void**)&p_al,   g_alpha);
    cudaGetSymbolAddress((void**)&p_gp,   g_gatepre);
    cudaGetSymbolAddress((void**)&p_gH,   g_gatesH);
    cudaGetSymbolAddress((void**)&p_xgc,  g_xgc);
    cudaGetSymbolAddress((void**)&p_W3,   g_Wcat3);
    cudaGetSymbolAddress((void**)&p_bb,   g_bihh);
    cudaGetSymbolAddress((void**)&p_es,   g_embseq);
    cudaGetSymbolAddress((void**)&p_eW,   g_embW);
    cudaGetSymbolAddress((void**)&p_part, g_part);

    // ---- precompute ----
    mean_kernel<<<dim3(F / 256, B), 256>>>(enc, p_feat);
    wcat3_kernel<<<dim3(H / 256, NCAT), 256>>>(Wha, Wfb, Whh, p_W3);
    bihh_kernel<<<dim3(4 * H / 256), 256>>>(bih, bhh, p_bb);
    embgather_kernel<<<dim3(E / 256, T * B), 256>>>(emb, caps, p_es);

    // h0/c0: M=128, N=512, K=2048, S=4 (Ks=512)
    tgemm(p_feat, Wh0, p_part, B, H, F, F, F, 4, nullptr);
    epi_hc_kernel<<<dim3(H / 256, B), 256>>>(p_part, 4, bh0, gamma_h, beta_h, p_h);
    tgemm(p_feat, Wc0, p_part, B, H, F, F, F, 4, nullptr);
    epi_hc_kernel<<<dim3(H / 256, B), 256>>>(p_part, 4, bc0, gamma_c, beta_c, p_c);

    // embW = embseq(2432x512) @ Wih[:, :E]^T   (304 CTAs, S=1)
    tgemm(p_es, Wih, p_eW, T * B, 4 * H, E, E, E + F, 1, nullptr);

    // feat_att = enc(25088x2048) @ Wfa^T + bfa (784 CTAs, S=1)
    tgemm(enc, Wfa, p_fa, B * P, NF, F, F, F, 1, bfa);

    // ---- timestep loop ----
    for (int t = 0; t < T; t++) {
        float* hprev = p_h + (size_t)(t & 1) * B * H;
        float* hnext = p_h + (size_t)((t + 1) & 1) * B * H;

        // h @ [Wha|Wfb|Whh]^T  (N=4608, K=512, S=4 -> 144 CTAs, Ks=128)
        tgemm(hprev, p_W3, p_part, B, NCAT, H, H, H, 4, nullptr);
        epi_hW_kernel<<<dim3(NCAT / 256, B), 256>>>(p_part, bha, bfb, p_bb, p_hW, p_gp, p_gH);

        att_e_kernel<<<dim3(B * P / 8), 256>>>(p_fa, p_hW, Wv, bv, p_e);
        softmax_kernel<<<dim3(B), 256>>>(p_e, p_al, out_alpha, lens, t);
        ctx_gate_kernel<<<dim3(F / 256, B), 256>>>(enc, p_al, p_gp, p_xgc);

        // xgc @ Wih[:, E:]^T  (N=2048, K=2048, S=8 -> 128 CTAs, Ks=256)
        tgemm(p_xgc, Wih + E, p_part, B, 4 * H, F, F, E + F, 8, nullptr);
        lstm_epi_kernel<<<dim3(B * H / 256), 256>>>(p_part, p_gH, p_eW, p_c, hnext, t);

        // preds = hnext @ Wfc^T  (N=10000, K=512, S=1 -> 79 CTAs)
        tgemm(hnext, Wfc, p_part, B, V, H, H, H, 1, nullptr);
        epi_preds_kernel<<<dim3((V + 255) / 256, B), 256>>>(p_part, bfc, lens, t, out_pred);
    }
}

// round 11
// speedup vs baseline: 2.4699x; 1.0532x over previous
#include <cuda_runtime.h>
#include <cuda_fp16.h>
#include <cstdint>
#include <cstddef>

#define B 128
#define P 196
#define F 2048
#define H 512
#define NF 512
#define E 512
#define V 10000
#define L 20
#define T 19
#define NCOMBO 14608      // 512 (Wha) + 2048 (Wfb) + 2048 (Whh) + 10000 (Wfc)
#define BN_SCALE 0.9999950000374997f   // 1/sqrt(1+1e-5)

typedef unsigned long long ull;

// ---------------- scratch (static device globals) ----------------
__device__ float g_feat[B * F];
__device__ float g_feat_att[(size_t)B * P * NF];       // 51.4 MB
__device__ float g_hbuf[B * H];
__device__ float g_c[B * H];
__device__ float g_hWha[B * NF];
__device__ float g_alpha[B * P];
__device__ float g_gatepre[B * F];
__device__ float g_gatesH[B * 4 * H];
__device__ float g_xgc[B * F];
__device__ float g_bihh[4 * H];
__device__ float g_embseq[(size_t)T * B * E];
__device__ float g_embW[(size_t)T * B * 4 * H];        // 19.9 MB
__device__ float g_part[4 * 1024 * 1024];              // split-K partials (16 MB)

// packed hi/lo f16 weight planes (pre-swizzled smem images, 32 KB per (nblk,chunk))
__device__ uint8_t g_pk_wcat4[(size_t)115 * 8 * 32768];   // 30.1 MB
__device__ uint8_t g_pk_wihF[(size_t)16 * 32 * 32768];    // 16.8 MB
__device__ uint8_t g_pk_wihE[(size_t)16 * 8 * 32768];     // 4.2 MB
__device__ uint8_t g_pk_wfa[(size_t)4 * 32 * 32768];      // 4.2 MB
__device__ uint8_t g_pk_wh0[(size_t)4 * 32 * 32768];
__device__ uint8_t g_pk_wc0[(size_t)4 * 32 * 32768];

__device__ __forceinline__ float sigmoidf(float x) { return 1.0f / (1.0f + expf(-x)); }

// ---------------- mma.sync helpers (non-'a' ISA) ----------------
__device__ __forceinline__ uint32_t smem_u32(const void* p) {
    uint32_t a;
    asm("{ .reg .u64 t; cvta.to.shared.u64 t, %1; cvt.u32.u64 %0, t; }" : "=r"(a) : "l"(p));
    return a;
}
__device__ __forceinline__ void ldsm4(uint32_t* r, uint32_t addr) {
    asm volatile("ldmatrix.sync.aligned.m8n8.x4.shared.b16 {%0,%1,%2,%3}, [%4];"
                 : "=r"(r[0]), "=r"(r[1]), "=r"(r[2]), "=r"(r[3]) : "r"(addr));
}
__device__ __forceinline__ void mma16816(float* c, const uint32_t* a, const uint32_t* b) {
    asm volatile(
        "mma.sync.aligned.m16n8k16.row.col.f32.f16.f16.f32 "
        "{%0,%1,%2,%3}, {%4,%5,%6,%7}, {%8,%9}, {%0,%1,%2,%3};"
        : "+f"(c[0]), "+f"(c[1]), "+f"(c[2]), "+f"(c[3])
        : "r"(a[0]), "r"(a[1]), "r"(a[2]), "r"(a[3]), "r"(b[0]), "r"(b[1]));
}
__device__ __forceinline__ uint32_t swz(uint32_t off) { return off ^ ((off >> 3) & 0x70); }
#define CP_ASYNC16(saddr, gaddr) \
    asm volatile("cp.async.cg.shared.global [%0], [%1], 16;" :: "r"(saddr), "l"(gaddr))

// split fp32 pair -> f16x2 hi word + f16x2 lo word
__device__ __forceinline__ void conv2h(float x, float y, uint32_t& hw, uint32_t& lw) {
    __half hx = __float2half_rn(x), hy = __float2half_rn(y);
    float rx = x - __half2float(hx);
    float ry = y - __half2float(hy);
    __half lx = __float2half_rn(rx), ly = __float2half_rn(ry);
    hw = ((uint32_t)__half_as_ushort(hy) << 16) | (uint32_t)__half_as_ushort(hx);
    lw = ((uint32_t)__half_as_ushort(ly) << 16) | (uint32_t)__half_as_ushort(lx);
}

// ---------------- weight pack kernel: fp32 (NxK,ldb) -> hi/lo planes, swizzled ------
// grid (NB, K/64), 256 threads. 32 KB per (nblk,chunk): hi 16K | lo 16K.
__global__ void pack_kernel(const float* __restrict__ src, uint8_t* __restrict__ dst,
                            int N, int ldb) {
    int nblk = blockIdx.x, chunk = blockIdx.y, tid = threadIdx.x;
    int r = tid >> 1, c0 = (tid & 1) * 32;
    int row = nblk * 128 + r;
    bool ok = row < N;
    const float* s = src + (size_t)row * ldb + chunk * 64 + c0;
    uint8_t* base = dst + ((size_t)nblk * gridDim.y + chunk) * 32768;
#pragma unroll
    for (int g = 0; g < 4; g++) {
        float4 v0 = ok ? *(const float4*)(s + g * 8)     : make_float4(0.f, 0.f, 0.f, 0.f);
        float4 v1 = ok ? *(const float4*)(s + g * 8 + 4) : make_float4(0.f, 0.f, 0.f, 0.f);
        uint32_t h0, l0, h1, l1, h2, l2, h3, l3;
        conv2h(v0.x, v0.y, h0, l0); conv2h(v0.z, v0.w, h1, l1);
        conv2h(v1.x, v1.y, h2, l2); conv2h(v1.z, v1.w, h3, l3);
        uint32_t sw = swz((uint32_t)r * 128 + (uint32_t)(c0 + g * 8) * 2);
        *(uint4*)(base + sw)         = make_uint4(h0, h1, h2, h3);
        *(uint4*)(base + 16384 + sw) = make_uint4(l0, l1, l2, l3);
    }
}

// ---------------- epilogue param block ----------------
struct EpiP {
    int mode;            // 0 partial, 1 bias-direct, 2 combo-scatter
    const float* bias;   // mode 1
    const float* bha; const float* bfb; const float* bihh; const float* bfc;
    const int* lens; int t;
    float* hWha; float* gatepre; float* gatesH; float* out_pred;
};

__device__ __forceinline__ void epi_store(const EpiP& ep, float* C, int M, int N, int z,
                                          int row, int col, float v) {
    if (col >= N) return;
    if (ep.mode == 0) {
        C[(size_t)z * M * N + (size_t)row * N + col] = v;
    } else if (ep.mode == 1) {
        C[(size_t)row * N + col] = ep.bias ? v + ep.bias[col] : v;
    } else {
        if (col < 512)       ep.hWha[row * 512 + col] = v + ep.bha[col];
        else if (col < 2560) ep.gatepre[row * 2048 + (col - 512)] = v + ep.bfb[col - 512];
        else if (col < 4608) ep.gatesH[row * 2048 + (col - 2560)] = v + ep.bihh[col - 2560];
        else {
            int n = col - 4608;
            float mf = (ep.t < ep.lens[row] - 1) ? 1.f : 0.f;
            ep.out_pred[((size_t)row * T + ep.t) * V + n] = (v + ep.bfc[n]) * mf;
        }
    }
}

// ============ packed-B split-f16 tensor GEMM: C = A(MxK,lda) @ Wpacked^T ============
// 128x128 tile, K-chunks of 64, double-buffered. B copied raw via cp.async (pre-split),
// A converted in-kernel. fp32 reg accumulation, 3 mma passes (AhBh+AhBl+AlBh).
#define PK_SMEM (2 * 65536)
__global__ __launch_bounds__(256, 1) void gemm_pk(
    const float* __restrict__ A, const uint8_t* __restrict__ Bp, float* __restrict__ C,
    int M, int N, int K, int lda, int kcTotal, EpiP ep)
{
    extern __shared__ char smem[];
    const uint32_t sbase = smem_u32(smem);
    const int tid = threadIdx.x, wid = tid >> 5, lane = tid & 31;
    const int bn = blockIdx.x * 128, bm = blockIdx.y * 128;
    const int z = blockIdx.z;
    const int Ks = K / (int)gridDim.z;
    const int nchunks = Ks >> 6;
    const int kchunk0 = (z * Ks) >> 6;

    const int r  = tid >> 1;
    const int c0 = (tid & 1) * 32;
    const float* aP = A + (size_t)(bm + r) * lda + (size_t)z * Ks + c0;
    const uint8_t* bBase = Bp + ((size_t)(bn >> 7) * kcTotal + kchunk0) * 32768
                         + (uint32_t)tid * 128;

    const int wm = wid & 3, wn = wid >> 2;
    const int m0 = wm * 32, n0w = wn * 64;
    const uint32_t arowb = (uint32_t)(m0 + (lane & 15)) * 128;
    const uint32_t acolp = ((lane >> 4) & 1) * 16;
    const uint32_t browb = (uint32_t)(n0w + (lane & 7) + ((lane & 16) ? 8 : 0)) * 128;
    const uint32_t bcolp = (lane & 8) ? 16u : 0u;

    float acc[2][8][4];
#pragma unroll
    for (int mi = 0; mi < 2; mi++)
#pragma unroll
        for (int ni = 0; ni < 8; ni++)
#pragma unroll
            for (int q = 0; q < 4; q++) acc[mi][ni][q] = 0.f;

    for (int ch = 0; ch < nchunks; ch++) {
        const int buf = ch & 1;
        const uint32_t base = (uint32_t)buf * 65536;
        if (ch >= 2) {
            asm volatile("bar.sync %0, %1;" :: "r"(1 + buf), "r"(512) : "memory");
        }
        // B: raw 32 KB copy (hi+lo planes) from packed global, async
        {
            const uint8_t* bsrc = bBase + (size_t)ch * 32768;
            const uint32_t bdst = sbase + base + 32768 + (uint32_t)tid * 128;
#pragma unroll
            for (int j = 0; j < 8; j++) CP_ASYNC16(bdst + j * 16, bsrc + j * 16);
            asm volatile("cp.async.commit_group;" ::: "memory");
        }
        // A: fp32 -> hi/lo f16 planes (overlaps with B copy)
        {
            const float* src = aP + ch * 64;
#pragma unroll
            for (int g = 0; g < 4; g++) {
                float4 v0 = *(const float4*)(src + g * 8);
                float4 v1 = *(const float4*)(src + g * 8 + 4);
                uint32_t h0, l0, h1, l1, h2, l2, h3, l3;
                conv2h(v0.x, v0.y, h0, l0); conv2h(v0.z, v0.w, h1, l1);
                conv2h(v1.x, v1.y, h2, l2); conv2h(v1.z, v1.w, h3, l3);
                uint32_t sw = swz((uint32_t)r * 128 + (uint32_t)(c0 + g * 8) * 2);
                *(uint4*)(smem + base + sw)         = make_uint4(h0, h1, h2, h3);
                *(uint4*)(smem + base + 16384 + sw) = make_uint4(l0, l1, l2, l3);
            }
        }
        asm volatile("cp.async.wait_group 0;" ::: "memory");
        __syncthreads();

        const uint32_t ahB = sbase + base;
        const uint32_t alB = ahB + 16384;
        const uint32_t bhB = ahB + 32768;
        const uint32_t blB = ahB + 49152;
#pragma unroll
        for (int ks = 0; ks < 4; ks++) {
            const uint32_t kb = (uint32_t)ks * 32;
            uint32_t ah[2][4], al[2][4];
#pragma unroll
            for (int mi = 0; mi < 2; mi++) {
                uint32_t ao = swz(arowb + (uint32_t)mi * 2048 + kb + acolp);
                ldsm4(ah[mi], ahB + ao);
                ldsm4(al[mi], alB + ao);
            }
            uint32_t bh[8][2], bl[8][2];
#pragma unroll
            for (int nj = 0; nj < 4; nj++) {
                uint32_t bo = swz(browb + (uint32_t)nj * 2048 + kb + bcolp);
                uint32_t t4[4];
                ldsm4(t4, bhB + bo);
                bh[2*nj][0] = t4[0]; bh[2*nj][1] = t4[1];
                bh[2*nj+1][0] = t4[2]; bh[2*nj+1][1] = t4[3];
                ldsm4(t4, blB + bo);
                bl[2*nj][0] = t4[0]; bl[2*nj][1] = t4[1];
                bl[2*nj+1][0] = t4[2]; bl[2*nj+1][1] = t4[3];
            }
#pragma unroll
            for (int mi = 0; mi < 2; mi++)
#pragma unroll
                for (int ni = 0; ni < 8; ni++) {
                    mma16816(acc[mi][ni], ah[mi], bh[ni]);
                    mma16816(acc[mi][ni], ah[mi], bl[ni]);
                    mma16816(acc[mi][ni], al[mi], bh[ni]);
                }
        }
        asm volatile("bar.arrive %0, %1;" :: "r"(1 + buf), "r"(512) : "memory");
    }

    // epilogue
#pragma unroll
    for (int mi = 0; mi < 2; mi++) {
        const int row1 = bm + m0 + mi * 16 + (lane >> 2);
        const int row2 = row1 + 8;
#pragma unroll
        for (int ni = 0; ni < 8; ni++) {
            const int col = bn + n0w + ni * 8 + 2 * (lane & 3);
            epi_store(ep, C, M, N, z, row1, col,     acc[mi][ni][0]);
            epi_store(ep, C, M, N, z, row1, col + 1, acc[mi][ni][1]);
            epi_store(ep, C, M, N, z, row2, col,     acc[mi][ni][2]);
            epi_store(ep, C, M, N, z, row2, col + 1, acc[mi][ni][3]);
        }
    }
}

// ---------------- small kernels ----------------
__global__ void mean_kernel(const float* __restrict__ enc, float* __restrict__ feat) {
    int f = blockIdx.x * 256 + threadIdx.x;   // grid (8, B)
    int b = blockIdx.y;
    const float* p0 = enc + (size_t)b * P * F + f;
    float s = 0.f;
#pragma unroll 4
    for (int p = 0; p < P; p++) s += p0[(size_t)p * F];
    feat[b * F + f] = s * (1.0f / (float)P);
}

__global__ void bihh_kernel(const float* __restrict__ bih, const float* __restrict__ bhh,
                            float* __restrict__ out) {
    int n = blockIdx.x * 256 + threadIdx.x;
    out[n] = bih[n] + bhh[n];
}

__global__ void embgather_kernel(const float* __restrict__ emb, const int* __restrict__ caps,
                                 float* __restrict__ embseq) {
    int col = blockIdx.x * 256 + threadIdx.x; // grid (2, T*B)
    int rrow = blockIdx.y;
    int t = rrow / B, b = rrow % B;
    int tok = caps[b * L + t];
    embseq[(size_t)rrow * E + col] = emb[(size_t)tok * E + col];
}

__global__ void epi_hc_kernel(const float* __restrict__ part, int S,
                              const float* __restrict__ bias, const float* __restrict__ gamma,
                              const float* __restrict__ beta, float* __restrict__ out) {
    int n = blockIdx.x * 256 + threadIdx.x;   // grid (2, B)
    int m = blockIdx.y;
    int idx = m * H + n;
    float s = 0.f;
    for (int zz = 0; zz < S; zz++) s += part[(size_t)zz * B * H + idx];
    float x = sigmoidf(s + bias[n]);
    out[idx] = gamma[n] * (x * BN_SCALE) + beta[n];
}

// fused attention energies + softmax; one CTA per batch element.
// bv dropped (constant shift cancels in softmax).
__global__ __launch_bounds__(256) void att_softmax_kernel(
    const float* __restrict__ fa, const float* __restrict__ hw,
    const float* __restrict__ Wv, float* __restrict__ alpha,
    float* __restrict__ out_alpha, const int* __restrict__ lens, int t)
{
    __shared__ float shw[512], swv[512], se[224], red[256];
    int b = blockIdx.x, tid = threadIdx.x, wid = tid >> 5, lane = tid & 31;
    if (tid < 128) {
        ((float4*)shw)[tid] = ((const float4*)(hw + b * 512))[tid];
        ((float4*)swv)[tid] = ((const float4*)Wv)[tid];
    }
    __syncthreads();
    for (int p = wid; p < P; p += 8) {
        const float* fr = fa + ((size_t)b * P + p) * 512;
        float s = 0.f;
#pragma unroll
        for (int j = 0; j < 4; j++) {
            int c = j * 128 + lane * 4;
            float4 x = *(const float4*)(fr + c);
            float4 y = *(const float4*)(shw + c);
            float4 w = *(const float4*)(swv + c);
            s += fmaxf(x.x + y.x, 0.f) * w.x + fmaxf(x.y + y.y, 0.f) * w.y
               + fmaxf(x.z + y.z, 0.f) * w.z + fmaxf(x.w + y.w, 0.f) * w.w;
        }
#pragma unroll
        for (int o = 16; o; o >>= 1) s += __shfl_xor_sync(0xffffffffu, s, o);
        if (lane == 0) se[p] = s;
    }
    __syncthreads();
    float v = (tid < P) ? se[tid] : -1e30f;
    red[tid] = v; __syncthreads();
    for (int o = 128; o; o >>= 1) { if (tid < o) red[tid] = fmaxf(red[tid], red[tid + o]); __syncthreads(); }
    float mx = red[0]; __syncthreads();
    float ex = (tid < P) ? expf(v - mx) : 0.f;
    red[tid] = ex; __syncthreads();
    for (int o = 128; o; o >>= 1) { if (tid < o) red[tid] += red[tid + o]; __syncthreads(); }
    float inv = 1.0f / red[0];
    if (tid < P) {
        float a = ex * inv;
        alpha[b * P + tid] = a;
        float mf = (t < lens[b] - 1) ? 1.f : 0.f;
        out_alpha[((size_t)b * T + t) * P + tid] = a * mf;
    }
}

// fused: context over P, then xgc = sigmoid(gatepre) * ctx
__global__ void ctx_gate_kernel(const float* __restrict__ enc, const float* __restrict__ alpha,
                                const float* __restrict__ gatepre, float* __restrict__ xgc) {
    __shared__ float sa[P];
    int b = blockIdx.y;                       // grid (8, B)
    int f = blockIdx.x * 256 + threadIdx.x;
    if (threadIdx.x < P) sa[threadIdx.x] = alpha[b * P + threadIdx.x];
    __syncthreads();
    const float* ep = enc + (size_t)b * P * F + f;
    float acc = 0.f;
#pragma unroll 4
    for (int p = 0; p < P; p++) acc += ep[(size_t)p * F] * sa[p];
    int idx = b * F + f;
    xgc[idx] = sigmoidf(gatepre[idx]) * acc;
}

// sums S=8 partials of xgc@WihF^T, adds gatesH + embW[t], runs LSTM cell
__global__ void lstm_epi_kernel(const float* __restrict__ part, const float* __restrict__ gatesH,
                                const float* __restrict__ embW, float* __restrict__ c,
                                float* __restrict__ hnext, int t) {
    int idx = blockIdx.x * 256 + threadIdx.x; // grid (B*H/256)
    int b = idx >> 9, j = idx & 511;
    float g4[4];
#pragma unroll
    for (int gi = 0; gi < 4; gi++) {
        int col = gi * 512 + j;
        float s = gatesH[b * 2048 + col] + embW[((size_t)t * B + b) * 2048 + col];
#pragma unroll
        for (int zz = 0; zz < 8; zz++) s += part[(size_t)zz * B * 2048 + b * 2048 + col];
        g4[gi] = s;
    }
    float ig = sigmoidf(g4[0]), fg = sigmoidf(g4[1]);
    float gg = tanhf(g4[2]),    og = sigmoidf(g4[3]);
    float cn = fg * c[idx] + ig * gg;
    c[idx] = cn;
    hnext[idx] = og * tanhf(cn);
}

// ---------------- host ----------------
static EpiP ep_partial() {
    EpiP e = {}; e.mode = 0; return e;
}
static EpiP ep_bias(const float* bias) {
    EpiP e = {}; e.mode = 1; e.bias = bias; return e;
}

static void gemm_launch(const float* A, const uint8_t* Bp, float* C, int M, int N, int K,
                        int lda, int kcTotal, int S, EpiP ep) {
    dim3 grid((N + 127) / 128, M / 128, S);
    gemm_pk<<<grid, 256, PK_SMEM>>>(A, Bp, C, M, N, K, lda, kcTotal, ep);
}

extern "C" void kernel_launch(void* const* d_in, const int* in_sizes, int n_in,
                              void* d_out, int out_size) {
    const float* enc     = (const float*)d_in[0];
    const float* emb     = (const float*)d_in[1];
    const float* Wfa     = (const float*)d_in[2];
    const float* bfa     = (const float*)d_in[3];
    const float* Wha     = (const float*)d_in[4];
    const float* bha     = (const float*)d_in[5];
    const float* Wv      = (const float*)d_in[6];
    // d_in[7] = bv (cancels in softmax)
    const float* Wh0     = (const float*)d_in[8];
    const float* bh0     = (const float*)d_in[9];
    const float* Wc0     = (const float*)d_in[10];
    const float* bc0     = (const float*)d_in[11];
    const float* gamma_h = (const float*)d_in[12];
    const float* beta_h  = (const float*)d_in[13];
    const float* gamma_c = (const float*)d_in[14];
    const float* beta_c  = (const float*)d_in[15];
    const float* Wfb     = (const float*)d_in[16];
    const float* bfb     = (const float*)d_in[17];
    const float* Wih     = (const float*)d_in[18];
    const float* Whh     = (const float*)d_in[19];
    const float* bih     = (const float*)d_in[20];
    const float* bhh     = (const float*)d_in[21];
    const float* Wfc     = (const float*)d_in[22];
    const float* bfc     = (const float*)d_in[23];
    const int*   caps    = (const int*)d_in[24];
    const int*   lens    = (const int*)d_in[25];

    float* out_pred  = (float*)d_out;
    float* out_alpha = out_pred + (size_t)B * T * V;

    cudaFuncSetAttribute(gemm_pk, cudaFuncAttributeMaxDynamicSharedMemorySize, PK_SMEM);

    float *p_feat, *p_fa, *p_h, *p_c, *p_hW, *p_al, *p_gp, *p_gH, *p_xgc,
          *p_bb, *p_es, *p_eW, *p_part;
    uint8_t *pk_wcat4, *pk_wihF, *pk_wihE, *pk_wfa, *pk_wh0, *pk_wc0;
    cudaGetSymbolAddress((void**)&p_feat, g_feat);
    cudaGetSymbolAddress((void**)&p_fa,   g_feat_att);
    cudaGetSymbolAddress((void**)&p_h,    g_hbuf);
    cudaGetSymbolAddress((void**)&p_c,    g_c);
    cudaGetSymbolAddress((void**)&p_hW,   g_hWha);
    cudaGetSymbolAddress((void**)&p_al,   g_alpha);
    cudaGetSymbolAddress((void**)&p_gp,   g_gatepre);
    cudaGetSymbolAddress((void**)&p_gH,   g_gatesH);
    cudaGetSymbolAddress((void**)&p_xgc,  g_xgc);
    cudaGetSymbolAddress((void**)&p_bb,   g_bihh);
    cudaGetSymbolAddress((void**)&p_es,   g_embseq);
    cudaGetSymbolAddress((void**)&p_eW,   g_embW);
    cudaGetSymbolAddress((void**)&p_part, g_part);
    cudaGetSymbolAddress((void**)&pk_wcat4, g_pk_wcat4);
    cudaGetSymbolAddress((void**)&pk_wihF, g_pk_wihF);
    cudaGetSymbolAddress((void**)&pk_wihE, g_pk_wihE);
    cudaGetSymbolAddress((void**)&pk_wfa, g_pk_wfa);
    cudaGetSymbolAddress((void**)&pk_wh0, g_pk_wh0);
    cudaGetSymbolAddress((void**)&pk_wc0, g_pk_wc0);

    // ---- precompute: pack all weights into hi/lo f16 smem-image planes ----
    pack_kernel<<<dim3(4, 32), 256>>>(Wfa, pk_wfa, NF, F);
    pack_kernel<<<dim3(4, 32), 256>>>(Wh0, pk_wh0, H, F);
    pack_kernel<<<dim3(4, 32), 256>>>(Wc0, pk_wc0, H, F);
    pack_kernel<<<dim3(16, 8), 256>>>(Wih, pk_wihE, 4 * H, E + F);                  // cols [0,E)
    pack_kernel<<<dim3(16, 32), 256>>>(Wih + E, pk_wihF, 4 * H, E + F);             // cols [E,E+F)
    // Wcat4 = [Wha | Wfb | Whh | Wfc], K=512, KC=8, blocks 0..114
    pack_kernel<<<dim3(4, 8), 256>>>(Wha, pk_wcat4, 512, H);
    pack_kernel<<<dim3(16, 8), 256>>>(Wfb, pk_wcat4 + (size_t)4 * 8 * 32768, 2048, H);
    pack_kernel<<<dim3(16, 8), 256>>>(Whh, pk_wcat4 + (size_t)20 * 8 * 32768, 2048, H);
    pack_kernel<<<dim3(79, 8), 256>>>(Wfc, pk_wcat4 + (size_t)36 * 8 * 32768, V, H);

    mean_kernel<<<dim3(F / 256, B), 256>>>(enc, p_feat);
    bihh_kernel<<<dim3(4 * H / 256), 256>>>(bih, bhh, p_bb);
    embgather_kernel<<<dim3(E / 256, T * B), 256>>>(emb, caps, p_es);

    // h0/c0: M=128, N=512, K=2048, S=4
    gemm_launch(p_feat, pk_wh0, p_part, B, H, F, F, 32, 4, ep_partial());
    epi_hc_kernel<<<dim3(H / 256, B), 256>>>(p_part, 4, bh0, gamma_h, beta_h, p_h);
    gemm_launch(p_feat, pk_wc0, p_part, B, H, F, F, 32, 4, ep_partial());
    epi_hc_kernel<<<dim3(H / 256, B), 256>>>(p_part, 4, bc0, gamma_c, beta_c, p_c);

    // embW = embseq(2432x512) @ Wih[:, :E]^T  (mode1, no bias)
    gemm_launch(p_es, pk_wihE, p_eW, T * B, 4 * H, E, E, 8, 1, ep_bias(nullptr));

    // feat_att = enc(25088x2048) @ Wfa^T + bfa
    gemm_launch(enc, pk_wfa, p_fa, B * P, NF, F, F, 32, 1, ep_bias(bfa));

    // initial h-side projections from h0 (combo, first 36 blocks only; t=-1 -> no preds cols)
    {
        EpiP ep = {}; ep.mode = 2;
        ep.bha = bha; ep.bfb = bfb; ep.bihh = p_bb; ep.bfc = bfc;
        ep.lens = lens; ep.t = -1;
        ep.hWha = p_hW; ep.gatepre = p_gp; ep.gatesH = p_gH; ep.out_pred = out_pred;
        gemm_launch(p_h, pk_wcat4, nullptr, B, 4608, H, H, 8, 1, ep);
    }

    // ---- timestep loop: 5 launches per step ----
    for (int t = 0; t < T; t++) {
        att_softmax_kernel<<<dim3(B), 256>>>(p_fa, p_hW, Wv, p_al, out_alpha, lens, t);
        ctx_gate_kernel<<<dim3(F / 256, B), 256>>>(enc, p_al, p_gp, p_xgc);

        // xgc @ Wih[:, E:]^T  (N=2048, K=2048, S=8 -> 128 CTAs)
        gemm_launch(p_xgc, pk_wihF, p_part, B, 4 * H, F, F, 32, 8, ep_partial());
        lstm_epi_kernel<<<dim3(B * H / 256), 256>>>(p_part, p_gH, p_eW, p_c, p_h, t);

        // combo: h @ [Wha|Wfb|Whh|Wfc]^T -> hWha/gatepre/gatesH (t+1) + masked preds(t)
        EpiP ep = {}; ep.mode = 2;
        ep.bha = bha; ep.bfb = bfb; ep.bihh = p_bb; ep.bfc = bfc;
        ep.lens = lens; ep.t = t;
        ep.hWha = p_hW; ep.gatepre = p_gp; ep.gatesH = p_gH; ep.out_pred = out_pred;
        gemm_launch(p_h, pk_wcat4, nullptr, B, NCOMBO, H, H, 8, 1, ep);
    }
}

// round 13
// speedup vs baseline: 2.7654x; 1.1197x over previous
#include <cuda_runtime.h>
#include <cuda_fp16.h>
#include <cstdint>
#include <cstddef>

#define B 128
#define P 196
#define F 2048
#define H 512
#define NF 512
#define E 512
#define V 10000
#define L 20
#define T 19
#define NCOMBO 14608      // 512 (Wha) + 2048 (Wfb) + 2048 (Whh) + 10000 (Wfc)
#define BN_SCALE 0.9999950000374997f   // 1/sqrt(1+1e-5)

typedef unsigned long long ull;

// ---------------- scratch (static device globals) ----------------
__device__ float g_feat[B * F];
__device__ float g_feat_att[(size_t)B * P * NF];       // 51.4 MB
__device__ float g_hbuf[B * H];
__device__ float g_c[B * H];
__device__ float g_hWha[B * NF];
__device__ float g_e[B * P];
__device__ float g_alpha[B * P];
__device__ float g_gatepre[B * F];
__device__ float g_gatesH[B * 4 * H];
__device__ float g_xgc[B * F];
__device__ float g_bihh[4 * H];
__device__ float g_embseq[(size_t)T * B * E];
__device__ float g_embW[(size_t)T * B * 4 * H];        // 19.9 MB
__device__ float g_part[4 * 1024 * 1024];              // split-K partials (16 MB)
__device__ __half g_ench[(size_t)B * P * F];           // fp16 enc copy, 102.8 MB

// packed hi/lo f16 weight planes (pre-swizzled smem images, 32 KB per (nblk,chunk))
__device__ uint8_t g_pk_wcat4[(size_t)115 * 8 * 32768];   // 30.1 MB
__device__ uint8_t g_pk_wihF[(size_t)16 * 32 * 32768];    // 16.8 MB
__device__ uint8_t g_pk_wihE[(size_t)16 * 8 * 32768];     // 4.2 MB
__device__ uint8_t g_pk_wfa[(size_t)4 * 32 * 32768];      // 4.2 MB
__device__ uint8_t g_pk_wh0[(size_t)4 * 32 * 32768];
__device__ uint8_t g_pk_wc0[(size_t)4 * 32 * 32768];

__device__ __forceinline__ float sigmoidf(float x) { return 1.0f / (1.0f + expf(-x)); }

__device__ __forceinline__ uint32_t h2u(__half2 h) {
    uint32_t u;
    memcpy(&u, &h, 4);
    return u;
}

// ---------------- mma.sync helpers (non-'a' ISA) ----------------
__device__ __forceinline__ uint32_t smem_u32(const void* p) {
    uint32_t a;
    asm("{ .reg .u64 t; cvta.to.shared.u64 t, %1; cvt.u32.u64 %0, t; }" : "=r"(a) : "l"(p));
    return a;
}
__device__ __forceinline__ void ldsm4(uint32_t* r, uint32_t addr) {
    asm volatile("ldmatrix.sync.aligned.m8n8.x4.shared.b16 {%0,%1,%2,%3}, [%4];"
                 : "=r"(r[0]), "=r"(r[1]), "=r"(r[2]), "=r"(r[3]) : "r"(addr));
}
__device__ __forceinline__ void mma16816(float* c, const uint32_t* a, const uint32_t* b) {
    asm volatile(
        "mma.sync.aligned.m16n8k16.row.col.f32.f16.f16.f32 "
        "{%0,%1,%2,%3}, {%4,%5,%6,%7}, {%8,%9}, {%0,%1,%2,%3};"
        : "+f"(c[0]), "+f"(c[1]), "+f"(c[2]), "+f"(c[3])
        : "r"(a[0]), "r"(a[1]), "r"(a[2]), "r"(a[3]), "r"(b[0]), "r"(b[1]));
}
__device__ __forceinline__ uint32_t swz(uint32_t off) { return off ^ ((off >> 3) & 0x70); }
#define CP_ASYNC16(saddr, gaddr) \
    asm volatile("cp.async.cg.shared.global [%0], [%1], 16;" :: "r"(saddr), "l"(gaddr))

// split fp32 pair -> f16x2 hi word + f16x2 lo word
__device__ __forceinline__ void conv2h(float x, float y, uint32_t& hw, uint32_t& lw) {
    __half hx = __float2half_rn(x), hy = __float2half_rn(y);
    float rx = x - __half2float(hx);
    float ry = y - __half2float(hy);
    __half lx = __float2half_rn(rx), ly = __float2half_rn(ry);
    hw = ((uint32_t)__half_as_ushort(hy) << 16) | (uint32_t)__half_as_ushort(hx);
    lw = ((uint32_t)__half_as_ushort(ly) << 16) | (uint32_t)__half_as_ushort(lx);
}

// ---------------- weight pack kernel: fp32 (NxK,ldb) -> hi/lo planes, swizzled ------
__global__ void pack_kernel(const float* __restrict__ src, uint8_t* __restrict__ dst,
                            int N, int ldb) {
    int nblk = blockIdx.x, chunk = blockIdx.y, tid = threadIdx.x;
    int r = tid >> 1, c0 = (tid & 1) * 32;
    int row = nblk * 128 + r;
    bool ok = row < N;
    const float* s = src + (size_t)row * ldb + chunk * 64 + c0;
    uint8_t* base = dst + ((size_t)nblk * gridDim.y + chunk) * 32768;
#pragma unroll
    for (int g = 0; g < 4; g++) {
        float4 v0 = ok ? *(const float4*)(s + g * 8)     : make_float4(0.f, 0.f, 0.f, 0.f);
        float4 v1 = ok ? *(const float4*)(s + g * 8 + 4) : make_float4(0.f, 0.f, 0.f, 0.f);
        uint32_t h0, l0, h1, l1, h2, l2, h3, l3;
        conv2h(v0.x, v0.y, h0, l0); conv2h(v0.z, v0.w, h1, l1);
        conv2h(v1.x, v1.y, h2, l2); conv2h(v1.z, v1.w, h3, l3);
        uint32_t sw = swz((uint32_t)r * 128 + (uint32_t)(c0 + g * 8) * 2);
        *(uint4*)(base + sw)         = make_uint4(h0, h1, h2, h3);
        *(uint4*)(base + 16384 + sw) = make_uint4(l0, l1, l2, l3);
    }
}

// ---------------- epilogue param block ----------------
struct EpiP {
    int mode;            // 0 partial, 1 bias-direct, 2 combo-scatter
    const float* bias;   // mode 1
    const float* bha; const float* bfb; const float* bihh; const float* bfc;
    const int* lens; int t;
    float* hWha; float* gatepre; float* gatesH; float* out_pred;
};

__device__ __forceinline__ void epi_store(const EpiP& ep, float* C, int M, int N, int z,
                                          int row, int col, float v) {
    if (col >= N) return;
    if (ep.mode == 0) {
        C[(size_t)z * M * N + (size_t)row * N + col] = v;
    } else if (ep.mode == 1) {
        C[(size_t)row * N + col] = ep.bias ? v + ep.bias[col] : v;
    } else {
        if (col < 512)       ep.hWha[row * 512 + col] = v + ep.bha[col];
        else if (col < 2560) ep.gatepre[row * 2048 + (col - 512)] = v + ep.bfb[col - 512];
        else if (col < 4608) ep.gatesH[row * 2048 + (col - 2560)] = v + ep.bihh[col - 2560];
        else {
            int n = col - 4608;
            float mf = (ep.t < ep.lens[row] - 1) ? 1.f : 0.f;
            ep.out_pred[((size_t)row * T + ep.t) * V + n] = (v + ep.bfc[n]) * mf;
        }
    }
}

// ============ packed-B split-f16 tensor GEMM: C = A(MxK,lda) @ Wpacked^T ============
#define PK_SMEM (2 * 65536)
__global__ __launch_bounds__(256, 1) void gemm_pk(
    const float* __restrict__ A, const uint8_t* __restrict__ Bp, float* __restrict__ C,
    int M, int N, int K, int lda, int kcTotal, EpiP ep)
{
    extern __shared__ char smem[];
    const uint32_t sbase = smem_u32(smem);
    const int tid = threadIdx.x, wid = tid >> 5, lane = tid & 31;
    const int bn = blockIdx.x * 128, bm = blockIdx.y * 128;
    const int z = blockIdx.z;
    const int Ks = K / (int)gridDim.z;
    const int nchunks = Ks >> 6;
    const int kchunk0 = (z * Ks) >> 6;

    const int r  = tid >> 1;
    const int c0 = (tid & 1) * 32;
    const float* aP = A + (size_t)(bm + r) * lda + (size_t)z * Ks + c0;
    const uint8_t* bBase = Bp + ((size_t)(bn >> 7) * kcTotal + kchunk0) * 32768
                         + (uint32_t)tid * 128;

    const int wm = wid & 3, wn = wid >> 2;
    const int m0 = wm * 32, n0w = wn * 64;
    const uint32_t arowb = (uint32_t)(m0 + (lane & 15)) * 128;
    const uint32_t acolp = ((lane >> 4) & 1) * 16;
    const uint32_t browb = (uint32_t)(n0w + (lane & 7) + ((lane & 16) ? 8 : 0)) * 128;
    const uint32_t bcolp = (lane & 8) ? 16u : 0u;

    float acc[2][8][4];
#pragma unroll
    for (int mi = 0; mi < 2; mi++)
#pragma unroll
        for (int ni = 0; ni < 8; ni++)
#pragma unroll
            for (int q = 0; q < 4; q++) acc[mi][ni][q] = 0.f;

    for (int ch = 0; ch < nchunks; ch++) {
        const int buf = ch & 1;
        const uint32_t base = (uint32_t)buf * 65536;
        if (ch >= 2) {
            asm volatile("bar.sync %0, %1;" :: "r"(1 + buf), "r"(512) : "memory");
        }
        {
            const uint8_t* bsrc = bBase + (size_t)ch * 32768;
            const uint32_t bdst = sbase + base + 32768 + (uint32_t)tid * 128;
#pragma unroll
            for (int j = 0; j < 8; j++) CP_ASYNC16(bdst + j * 16, bsrc + j * 16);
            asm volatile("cp.async.commit_group;" ::: "memory");
        }
        {
            const float* src = aP + ch * 64;
#pragma unroll
            for (int g = 0; g < 4; g++) {
                float4 v0 = *(const float4*)(src + g * 8);
                float4 v1 = *(const float4*)(src + g * 8 + 4);
                uint32_t h0, l0, h1, l1, h2, l2, h3, l3;
                conv2h(v0.x, v0.y, h0, l0); conv2h(v0.z, v0.w, h1, l1);
                conv2h(v1.x, v1.y, h2, l2); conv2h(v1.z, v1.w, h3, l3);
                uint32_t sw = swz((uint32_t)r * 128 + (uint32_t)(c0 + g * 8) * 2);
                *(uint4*)(smem + base + sw)         = make_uint4(h0, h1, h2, h3);
                *(uint4*)(smem + base + 16384 + sw) = make_uint4(l0, l1, l2, l3);
            }
        }
        asm volatile("cp.async.wait_group 0;" ::: "memory");
        __syncthreads();

        const uint32_t ahB = sbase + base;
        const uint32_t alB = ahB + 16384;
        const uint32_t bhB = ahB + 32768;
        const uint32_t blB = ahB + 49152;
#pragma unroll
        for (int ks = 0; ks < 4; ks++) {
            const uint32_t kb = (uint32_t)ks * 32;
            uint32_t ah[2][4], al[2][4];
#pragma unroll
            for (int mi = 0; mi < 2; mi++) {
                uint32_t ao = swz(arowb + (uint32_t)mi * 2048 + kb + acolp);
                ldsm4(ah[mi], ahB + ao);
                ldsm4(al[mi], alB + ao);
            }
            uint32_t bh[8][2], bl[8][2];
#pragma unroll
            for (int nj = 0; nj < 4; nj++) {
                uint32_t bo = swz(browb + (uint32_t)nj * 2048 + kb + bcolp);
                uint32_t t4[4];
                ldsm4(t4, bhB + bo);
                bh[2*nj][0] = t4[0]; bh[2*nj][1] = t4[1];
                bh[2*nj+1][0] = t4[2]; bh[2*nj+1][1] = t4[3];
                ldsm4(t4, blB + bo);
                bl[2*nj][0] = t4[0]; bl[2*nj][1] = t4[1];
                bl[2*nj+1][0] = t4[2]; bl[2*nj+1][1] = t4[3];
            }
#pragma unroll
            for (int mi = 0; mi < 2; mi++)
#pragma unroll
                for (int ni = 0; ni < 8; ni++) {
                    mma16816(acc[mi][ni], ah[mi], bh[ni]);
                    mma16816(acc[mi][ni], ah[mi], bl[ni]);
                    mma16816(acc[mi][ni], al[mi], bh[ni]);
                }
        }
        asm volatile("bar.arrive %0, %1;" :: "r"(1 + buf), "r"(512) : "memory");
    }

#pragma unroll
    for (int mi = 0; mi < 2; mi++) {
        const int row1 = bm + m0 + mi * 16 + (lane >> 2);
        const int row2 = row1 + 8;
#pragma unroll
        for (int ni = 0; ni < 8; ni++) {
            const int col = bn + n0w + ni * 8 + 2 * (lane & 3);
            epi_store(ep, C, M, N, z, row1, col,     acc[mi][ni][0]);
            epi_store(ep, C, M, N, z, row1, col + 1, acc[mi][ni][1]);
            epi_store(ep, C, M, N, z, row2, col,     acc[mi][ni][2]);
            epi_store(ep, C, M, N, z, row2, col + 1, acc[mi][ni][3]);
        }
    }
}

// ---------------- small kernels ----------------
__global__ void enc2h_kernel(const float* __restrict__ enc, __half* __restrict__ ench) {
    size_t i = ((size_t)blockIdx.x * 256 + threadIdx.x) * 8;   // grid (B*P*F/2048)
    float4 v0 = *(const float4*)(enc + i);
    float4 v1 = *(const float4*)(enc + i + 4);
    __half2 h0 = __floats2half2_rn(v0.x, v0.y);
    __half2 h1 = __floats2half2_rn(v0.z, v0.w);
    __half2 h2 = __floats2half2_rn(v1.x, v1.y);
    __half2 h3 = __floats2half2_rn(v1.z, v1.w);
    *(uint4*)(ench + i) = make_uint4(h2u(h0), h2u(h1), h2u(h2), h2u(h3));
}

__global__ void mean_kernel(const float* __restrict__ enc, float* __restrict__ feat) {
    int f = blockIdx.x * 256 + threadIdx.x;   // grid (8, B)
    int b = blockIdx.y;
    const float* p0 = enc + (size_t)b * P * F + f;
    float s = 0.f;
#pragma unroll 4
    for (int p = 0; p < P; p++) s += p0[(size_t)p * F];
    feat[b * F + f] = s * (1.0f / (float)P);
}

__global__ void bihh_kernel(const float* __restrict__ bih, const float* __restrict__ bhh,
                            float* __restrict__ out) {
    int n = blockIdx.x * 256 + threadIdx.x;
    out[n] = bih[n] + bhh[n];
}

__global__ void embgather_kernel(const float* __restrict__ emb, const int* __restrict__ caps,
                                 float* __restrict__ embseq) {
    int col = blockIdx.x * 256 + threadIdx.x; // grid (2, T*B)
    int rrow = blockIdx.y;
    int t = rrow / B, b = rrow % B;
    int tok = caps[b * L + t];
    embseq[(size_t)rrow * E + col] = emb[(size_t)tok * E + col];
}

__global__ void epi_hc_kernel(const float* __restrict__ part, int S,
                              const float* __restrict__ bias, const float* __restrict__ gamma,
                              const float* __restrict__ beta, float* __restrict__ out) {
    int n = blockIdx.x * 256 + threadIdx.x;   // grid (2, B)
    int m = blockIdx.y;
    int idx = m * H + n;
    float s = 0.f;
    for (int zz = 0; zz < S; zz++) s += part[(size_t)zz * B * H + idx];
    float x = sigmoidf(s + bias[n]);
    out[idx] = gamma[n] * (x * BN_SCALE) + beta[n];
}

// e[b,p] = sum_n relu(fa[b,p,n] + hWha[b,n]) * Wv[n]   (bv dropped; cancels in softmax)
__global__ __launch_bounds__(256) void att_e_kernel(
    const float* __restrict__ fa, const float* __restrict__ hw,
    const float* __restrict__ Wv, float* __restrict__ e) {
    int warp = threadIdx.x >> 5, lane = threadIdx.x & 31;
    int gid = blockIdx.x * 8 + warp;          // grid (B*P/8) = 3136 warps
    int b = gid / P;
    const float4* fav = (const float4*)(fa + (size_t)gid * NF);
    const float4* hwv = (const float4*)(hw + (size_t)b * NF);
    const float4* wvv = (const float4*)Wv;
    float s = 0.f;
#pragma unroll
    for (int rr = 0; rr < 4; rr++) {
        int i = lane + rr * 32;
        float4 x = fav[i], y = hwv[i], w = wvv[i];
        s += fmaxf(x.x + y.x, 0.f) * w.x + fmaxf(x.y + y.y, 0.f) * w.y
           + fmaxf(x.z + y.z, 0.f) * w.z + fmaxf(x.w + y.w, 0.f) * w.w;
    }
#pragma unroll
    for (int o = 16; o; o >>= 1) s += __shfl_xor_sync(0xffffffffu, s, o);
    if (lane == 0) e[gid] = s;
}

__global__ void softmax_kernel(const float* __restrict__ e, float* __restrict__ alpha,
                               float* __restrict__ out_alpha, const int* __restrict__ lens, int t) {
    int b = blockIdx.x;
    int p = threadIdx.x;
    __shared__ float red[256];
    float v = (p < P) ? e[b * P + p] : -1e30f;
    red[p] = v; __syncthreads();
    for (int o = 128; o; o >>= 1) { if (p < o) red[p] = fmaxf(red[p], red[p + o]); __syncthreads(); }
    float mx = red[0]; __syncthreads();
    float ex = (p < P) ? expf(v - mx) : 0.f;
    red[p] = ex; __syncthreads();
    for (int o = 128; o; o >>= 1) { if (p < o) red[p] += red[p + o]; __syncthreads(); }
    float inv = 1.0f / red[0];
    if (p < P) {
        float a = ex * inv;
        alpha[b * P + p] = a;
        float mf = (t < lens[b] - 1) ? 1.f : 0.f;
        out_alpha[((size_t)b * T + t) * P + p] = a * mf;
    }
}

// fused: context over P (fp16 enc), then xgc = sigmoid(gatepre) * ctx
__global__ __launch_bounds__(256) void ctx_gate_kernel(
    const __half* __restrict__ ench, const float* __restrict__ alpha,
    const float* __restrict__ gatepre, float* __restrict__ xgc) {
    __shared__ float sa[P];
    int b = blockIdx.y;                       // grid (4, B)
    int f2 = blockIdx.x * 256 + threadIdx.x;  // half2 column index
    if (threadIdx.x < P) sa[threadIdx.x] = alpha[b * P + threadIdx.x];
    __syncthreads();
    const __half2* ep = (const __half2*)(ench + (size_t)b * P * F) + f2;
    float ax = 0.f, ay = 0.f;
#pragma unroll 8
    for (int p = 0; p < P; p++) {
        float2 v = __half22float2(ep[(size_t)p * (F / 2)]);
        float a = sa[p];
        ax += v.x * a; ay += v.y * a;
    }
    int idx = b * F + f2 * 2;
    xgc[idx]     = sigmoidf(gatepre[idx])     * ax;
    xgc[idx + 1] = sigmoidf(gatepre[idx + 1]) * ay;
}

// sums S=8 partials of xgc@WihF^T, adds gatesH + embW[t], runs LSTM cell
__global__ void lstm_epi_kernel(const float* __restrict__ part, const float* __restrict__ gatesH,
                                const float* __restrict__ embW, float* __restrict__ c,
                                float* __restrict__ hnext, int t) {
    int idx = blockIdx.x * 256 + threadIdx.x; // grid (B*H/256)
    int b = idx >> 9, j = idx & 511;
    float g4[4];
#pragma unroll
    for (int gi = 0; gi < 4; gi++) {
        int col = gi * 512 + j;
        float s = gatesH[b * 2048 + col] + embW[((size_t)t * B + b) * 2048 + col];
#pragma unroll
        for (int zz = 0; zz < 8; zz++) s += part[(size_t)zz * B * 2048 + b * 2048 + col];
        g4[gi] = s;
    }
    float ig = sigmoidf(g4[0]), fg = sigmoidf(g4[1]);
    float gg = tanhf(g4[2]),    og = sigmoidf(g4[3]);
    float cn = fg * c[idx] + ig * gg;
    c[idx] = cn;
    hnext[idx] = og * tanhf(cn);
}

// ---------------- host ----------------
static EpiP ep_partial() { EpiP e = {}; e.mode = 0; return e; }
static EpiP ep_bias(const float* bias) { EpiP e = {}; e.mode = 1; e.bias = bias; return e; }

static void gemm_launch(const float* A, const uint8_t* Bp, float* C, int M, int N, int K,
                        int lda, int kcTotal, int S, EpiP ep) {
    dim3 grid((N + 127) / 128, M / 128, S);
    gemm_pk<<<grid, 256, PK_SMEM>>>(A, Bp, C, M, N, K, lda, kcTotal, ep);
}

extern "C" void kernel_launch(void* const* d_in, const int* in_sizes, int n_in,
                              void* d_out, int out_size) {
    const float* enc     = (const float*)d_in[0];
    const float* emb     = (const float*)d_in[1];
    const float* Wfa     = (const float*)d_in[2];
    const float* bfa     = (const float*)d_in[3];
    const float* Wha     = (const float*)d_in[4];
    const float* bha     = (const float*)d_in[5];
    const float* Wv      = (const float*)d_in[6];
    // d_in[7] = bv (cancels in softmax)
    const float* Wh0     = (const float*)d_in[8];
    const float* bh0     = (const float*)d_in[9];
    const float* Wc0     = (const float*)d_in[10];
    const float* bc0     = (const float*)d_in[11];
    const float* gamma_h = (const float*)d_in[12];
    const float* beta_h  = (const float*)d_in[13];
    const float* gamma_c = (const float*)d_in[14];
    const float* beta_c  = (const float*)d_in[15];
    const float* Wfb     = (const float*)d_in[16];
    const float* bfb     = (const float*)d_in[17];
    const float* Wih     = (const float*)d_in[18];
    const float* Whh     = (const float*)d_in[19];
    const float* bih     = (const float*)d_in[20];
    const float* bhh     = (const float*)d_in[21];
    const float* Wfc     = (const float*)d_in[22];
    const float* bfc     = (const float*)d_in[23];
    const int*   caps    = (const int*)d_in[24];
    const int*   lens    = (const int*)d_in[25];

    float* out_pred  = (float*)d_out;
    float* out_alpha = out_pred + (size_t)B * T * V;

    cudaFuncSetAttribute(gemm_pk, cudaFuncAttributeMaxDynamicSharedMemorySize, PK_SMEM);

    float *p_feat, *p_fa, *p_h, *p_c, *p_hW, *p_e, *p_al, *p_gp, *p_gH, *p_xgc,
          *p_bb, *p_es, *p_eW, *p_part;
    __half* p_ench;
    uint8_t *pk_wcat4, *pk_wihF, *pk_wihE, *pk_wfa, *pk_wh0, *pk_wc0;
    cudaGetSymbolAddress((void**)&p_feat, g_feat);
    cudaGetSymbolAddress((void**)&p_fa,   g_feat_att);
    cudaGetSymbolAddress((void**)&p_h,    g_hbuf);
    cudaGetSymbolAddress((void**)&p_c,    g_c);
    cudaGetSymbolAddress((void**)&p_hW,   g_hWha);
    cudaGetSymbolAddress((void**)&p_e,    g_e);
    cudaGetSymbolAddress((void**)&p_al,   g_alpha);
    cudaGetSymbolAddress((void**)&p_gp,   g_gatepre);
    cudaGetSymbolAddress((void**)&p_gH,   g_gatesH);
    cudaGetSymbolAddress((void**)&p_xgc,  g_xgc);
    cudaGetSymbolAddress((void**)&p_bb,   g_bihh);
    cudaGetSymbolAddress((void**)&p_es,   g_embseq);
    cudaGetSymbolAddress((void**)&p_eW,   g_embW);
    cudaGetSymbolAddress((void**)&p_part, g_part);
    cudaGetSymbolAddress((void**)&p_ench, g_ench);
    cudaGetSymbolAddress((void**)&pk_wcat4, g_pk_wcat4);
    cudaGetSymbolAddress((void**)&pk_wihF, g_pk_wihF);
    cudaGetSymbolAddress((void**)&pk_wihE, g_pk_wihE);
    cudaGetSymbolAddress((void**)&pk_wfa, g_pk_wfa);
    cudaGetSymbolAddress((void**)&pk_wh0, g_pk_wh0);
    cudaGetSymbolAddress((void**)&pk_wc0, g_pk_wc0);

    // ---- precompute ----
    enc2h_kernel<<<dim3((int)(((size_t)B * P * F) / 2048)), 256>>>(enc, p_ench);
    pack_kernel<<<dim3(4, 32), 256>>>(Wfa, pk_wfa, NF, F);
    pack_kernel<<<dim3(4, 32), 256>>>(Wh0, pk_wh0, H, F);
    pack_kernel<<<dim3(4, 32), 256>>>(Wc0, pk_wc0, H, F);
    pack_kernel<<<dim3(16, 8), 256>>>(Wih, pk_wihE, 4 * H, E + F);
    pack_kernel<<<dim3(16, 32), 256>>>(Wih + E, pk_wihF, 4 * H, E + F);
    pack_kernel<<<dim3(4, 8), 256>>>(Wha, pk_wcat4, 512, H);
    pack_kernel<<<dim3(16, 8), 256>>>(Wfb, pk_wcat4 + (size_t)4 * 8 * 32768, 2048, H);
    pack_kernel<<<dim3(16, 8), 256>>>(Whh, pk_wcat4 + (size_t)20 * 8 * 32768, 2048, H);
    pack_kernel<<<dim3(79, 8), 256>>>(Wfc, pk_wcat4 + (size_t)36 * 8 * 32768, V, H);

    mean_kernel<<<dim3(F / 256, B), 256>>>(enc, p_feat);
    bihh_kernel<<<dim3(4 * H / 256), 256>>>(bih, bhh, p_bb);
    embgather_kernel<<<dim3(E / 256, T * B), 256>>>(emb, caps, p_es);

    // h0/c0: M=128, N=512, K=2048, S=4
    gemm_launch(p_feat, pk_wh0, p_part, B, H, F, F, 32, 4, ep_partial());
    epi_hc_kernel<<<dim3(H / 256, B), 256>>>(p_part, 4, bh0, gamma_h, beta_h, p_h);
    gemm_launch(p_feat, pk_wc0, p_part, B, H, F, F, 32, 4, ep_partial());
    epi_hc_kernel<<<dim3(H / 256, B), 256>>>(p_part, 4, bc0, gamma_c, beta_c, p_c);

    // embW = embseq(2432x512) @ Wih[:, :E]^T
    gemm_launch(p_es, pk_wihE, p_eW, T * B, 4 * H, E, E, 8, 1, ep_bias(nullptr));

    // feat_att = enc(25088x2048) @ Wfa^T + bfa
    gemm_launch(enc, pk_wfa, p_fa, B * P, NF, F, F, 32, 1, ep_bias(bfa));

    // initial h-side projections from h0 (combo, 36 blocks; t=-1 -> no preds cols)
    {
        EpiP ep = {}; ep.mode = 2;
        ep.bha = bha; ep.bfb = bfb; ep.bihh = p_bb; ep.bfc = bfc;
        ep.lens = lens; ep.t = -1;
        ep.hWha = p_hW; ep.gatepre = p_gp; ep.gatesH = p_gH; ep.out_pred = out_pred;
        gemm_launch(p_h, pk_wcat4, nullptr, B, 4608, H, H, 8, 1, ep);
    }

    // ---- timestep loop: 6 launches per step ----
    for (int t = 0; t < T; t++) {
        att_e_kernel<<<dim3(B * P / 8), 256>>>(p_fa, p_hW, Wv, p_e);
        softmax_kernel<<<dim3(B), 256>>>(p_e, p_al, out_alpha, lens, t);
        ctx_gate_kernel<<<dim3(F / 512, B), 256>>>(p_ench, p_al, p_gp, p_xgc);

        // xgc @ Wih[:, E:]^T  (N=2048, K=2048, S=8 -> 128 CTAs)
        gemm_launch(p_xgc, pk_wihF, p_part, B, 4 * H, F, F, 32, 8, ep_partial());
        lstm_epi_kernel<<<dim3(B * H / 256), 256>>>(p_part, p_gH, p_eW, p_c, p_h, t);

        // combo: h @ [Wha|Wfb|Whh|Wfc]^T -> hWha/gatepre/gatesH (t+1) + masked preds(t)
        EpiP ep = {}; ep.mode = 2;
        ep.bha = bha; ep.bfb = bfb; ep.bihh = p_bb; ep.bfc = bfc;
        ep.lens = lens; ep.t = t;
        ep.hWha = p_hW; ep.gatepre = p_gp; ep.gatesH = p_gH; ep.out_pred = out_pred;
        gemm_launch(p_h, pk_wcat4, nullptr, B, NCOMBO, H, H, 8, 1, ep);
    }
}